// round 2
// baseline (speedup 1.0000x reference)
#include <cuda_runtime.h>
#include <cuda_bf16.h>
#include <math.h>

// Problem constants
#define S_LEN 2048
#define BATCH 2
#define DMODEL 1024
#define NH 16
#define DKH 64
#define MROWS (S_LEN * BATCH)   // 4096

// Scratch (allocation-free rule: __device__ globals)
__device__ float g_qkv[(size_t)MROWS * 3 * DMODEL];   // [4096, 3072]
__device__ float g_attn[(size_t)MROWS * DMODEL];      // [4096, 1024]

// ---------------------------------------------------------------------------
// SGEMM: C[m,n] = sum_k A[m,k] * B[n,k] (+ bias[n])
// A row-major [M,K], B row-major [N,K] (weights), C row-major [M,N]
// 128x128 tile, BK=8, 8x8 per-thread microtile, 256 threads.
// ---------------------------------------------------------------------------
__global__ __launch_bounds__(256) void sgemm_nt_kernel(
    const float* __restrict__ A, const float* __restrict__ B,
    const float* __restrict__ bias, float* __restrict__ C,
    int M, int N, int K)
{
    const int BM = 128, BN = 128, BK = 8;
    __shared__ float As[BK][BM];
    __shared__ float Bs[BK][BN];

    int tid = threadIdx.x;
    int mBase = blockIdx.y * BM;
    int nBase = blockIdx.x * BN;
    int tx = tid & 15;        // 0..15
    int ty = tid >> 4;        // 0..15

    float acc[8][8];
#pragma unroll
    for (int i = 0; i < 8; ++i)
#pragma unroll
        for (int j = 0; j < 8; ++j) acc[i][j] = 0.f;

    int loadRow = tid >> 1;          // 0..127
    int loadK4  = (tid & 1) * 4;     // 0 or 4
    const float* Aptr = A + (size_t)(mBase + loadRow) * K + loadK4;
    const float* Bptr = B + (size_t)(nBase + loadRow) * K + loadK4;

    for (int k0 = 0; k0 < K; k0 += BK) {
        float4 a4 = *(const float4*)(Aptr + k0);
        float4 b4 = *(const float4*)(Bptr + k0);
        As[loadK4 + 0][loadRow] = a4.x;
        As[loadK4 + 1][loadRow] = a4.y;
        As[loadK4 + 2][loadRow] = a4.z;
        As[loadK4 + 3][loadRow] = a4.w;
        Bs[loadK4 + 0][loadRow] = b4.x;
        Bs[loadK4 + 1][loadRow] = b4.y;
        Bs[loadK4 + 2][loadRow] = b4.z;
        Bs[loadK4 + 3][loadRow] = b4.w;
        __syncthreads();

#pragma unroll
        for (int kc = 0; kc < BK; ++kc) {
            float4 a0 = *(const float4*)&As[kc][ty * 8];
            float4 a1 = *(const float4*)&As[kc][ty * 8 + 4];
            float4 b0 = *(const float4*)&Bs[kc][tx * 8];
            float4 b1 = *(const float4*)&Bs[kc][tx * 8 + 4];
            float ar[8] = {a0.x, a0.y, a0.z, a0.w, a1.x, a1.y, a1.z, a1.w};
            float br[8] = {b0.x, b0.y, b0.z, b0.w, b1.x, b1.y, b1.z, b1.w};
#pragma unroll
            for (int i = 0; i < 8; ++i)
#pragma unroll
                for (int j = 0; j < 8; ++j)
                    acc[i][j] += ar[i] * br[j];
        }
        __syncthreads();
    }

#pragma unroll
    for (int i = 0; i < 8; ++i) {
        int m = mBase + ty * 8 + i;
        float* cp = C + (size_t)m * N + nBase + tx * 8;
#pragma unroll
        for (int j = 0; j < 8; j += 4) {
            float4 r;
            int ncol = nBase + tx * 8 + j;
            r.x = acc[i][j + 0] + (bias ? bias[ncol + 0] : 0.f);
            r.y = acc[i][j + 1] + (bias ? bias[ncol + 1] : 0.f);
            r.z = acc[i][j + 2] + (bias ? bias[ncol + 2] : 0.f);
            r.w = acc[i][j + 3] + (bias ? bias[ncol + 3] : 0.f);
            *(float4*)(cp + j) = r;
        }
    }
}

// ---------------------------------------------------------------------------
// Causal flash attention, fp32, one query row per thread.
// grid: (S/128, B*H), block: 128 threads.
// qkv layout: row (s*BATCH+b), col = which*DMODEL + h*DKH + d
// out layout g_attn: row (s*BATCH+b), col = h*DKH + d
// ---------------------------------------------------------------------------
__global__ __launch_bounds__(128) void attn_kernel(
    const float* __restrict__ qkv, float* __restrict__ out)
{
    const int KB = 64;            // kv tile rows
    int qb = blockIdx.x;
    int bh = blockIdx.y;
    int h = bh % NH;
    int b = bh / NH;
    int t = threadIdx.x;
    int qg = qb * 128 + t;        // global query index

    __shared__ float Ks[KB][68];  // 68-float stride: 16B-aligned rows, no store conflicts
    __shared__ float Vs[KB][68];

    // load q into registers, pre-scaled by 1/sqrt(dk)
    float q[DKH];
    {
        const float* qptr = qkv + ((size_t)(qg * BATCH + b)) * (3 * DMODEL) + h * DKH;
#pragma unroll
        for (int d = 0; d < DKH; d += 4) {
            float4 v = *(const float4*)(qptr + d);
            q[d + 0] = v.x * 0.125f;
            q[d + 1] = v.y * 0.125f;
            q[d + 2] = v.z * 0.125f;
            q[d + 3] = v.w * 0.125f;
        }
    }

    float m = -INFINITY, l = 0.f;
    float acc[DKH];
#pragma unroll
    for (int d = 0; d < DKH; ++d) acc[d] = 0.f;

    int kbEnd = (qb * 128 + 127) / KB;   // inclusive
    for (int kb = 0; kb <= kbEnd; ++kb) {
        __syncthreads();
        // cooperative load of K and V tiles (64 rows x 64 floats, float4)
        for (int i = t; i < KB * 16; i += 128) {
            int r = i >> 4;
            int c4 = (i & 15) * 4;
            int kvg = kb * KB + r;
            const float* kp = qkv + ((size_t)(kvg * BATCH + b)) * (3 * DMODEL)
                              + DMODEL + h * DKH + c4;
            float4 k4 = *(const float4*)kp;
            float4 v4 = *(const float4*)(kp + DMODEL);
            *(float4*)&Ks[r][c4] = k4;
            *(float4*)&Vs[r][c4] = v4;
        }
        __syncthreads();

        int validLimit = qg - kb * KB;     // j valid iff j <= validLimit
        if (validLimit < 0) continue;      // fully masked for this thread

#pragma unroll
        for (int chunk = 0; chunk < 4; ++chunk) {
            float s[16];
#pragma unroll
            for (int j = 0; j < 16; ++j) {
                int jj = chunk * 16 + j;
                float sum = 0.f;
#pragma unroll
                for (int d = 0; d < DKH; d += 4) {
                    float4 k4 = *(const float4*)&Ks[jj][d];
                    sum += q[d + 0] * k4.x;
                    sum += q[d + 1] * k4.y;
                    sum += q[d + 2] * k4.z;
                    sum += q[d + 3] * k4.w;
                }
                s[j] = (jj <= validLimit) ? sum : -INFINITY;
            }
            float cm = s[0];
#pragma unroll
            for (int j = 1; j < 16; ++j) cm = fmaxf(cm, s[j]);
            if (cm == -INFINITY) continue;  // fully masked chunk

            float mnew = fmaxf(m, cm);
            float corr = __expf(m - mnew);  // exp(-inf)=0 handles first block
            l *= corr;
#pragma unroll
            for (int d = 0; d < DKH; ++d) acc[d] *= corr;
            m = mnew;

#pragma unroll
            for (int j = 0; j < 16; ++j) {
                int jj = chunk * 16 + j;
                float p = __expf(s[j] - m);   // masked -> exp(-inf)=0
                l += p;
#pragma unroll
                for (int d = 0; d < DKH; d += 4) {
                    float4 v4 = *(const float4*)&Vs[jj][d];
                    acc[d + 0] += p * v4.x;
                    acc[d + 1] += p * v4.y;
                    acc[d + 2] += p * v4.z;
                    acc[d + 3] += p * v4.w;
                }
            }
        }
    }

    float inv = 1.f / l;
    float* op = out + ((size_t)(qg * BATCH + b)) * DMODEL + h * DKH;
#pragma unroll
    for (int d = 0; d < DKH; d += 4) {
        float4 r;
        r.x = acc[d + 0] * inv;
        r.y = acc[d + 1] * inv;
        r.z = acc[d + 2] * inv;
        r.w = acc[d + 3] * inv;
        *(float4*)(op + d) = r;
    }
}

// ---------------------------------------------------------------------------
extern "C" void kernel_launch(void* const* d_in, const int* in_sizes, int n_in,
                              void* d_out, int out_size)
{
    const float* x     = (const float*)d_in[0];   // [S,B,D]
    const float* w_qkv = (const float*)d_in[1];   // [3D,D]
    const float* w_out = (const float*)d_in[2];   // [D,D]
    const float* b_out = (const float*)d_in[3];   // [D]
    float* out = (float*)d_out;

    float* qkv;  cudaGetSymbolAddress((void**)&qkv,  g_qkv);
    float* attn; cudaGetSymbolAddress((void**)&attn, g_attn);

    // 1) QKV projection: [4096,1024] x [3072,1024]^T -> [4096,3072]
    {
        dim3 grid(3 * DMODEL / 128, MROWS / 128);
        sgemm_nt_kernel<<<grid, 256>>>(x, w_qkv, nullptr, qkv,
                                       MROWS, 3 * DMODEL, DMODEL);
    }
    // 2) Causal attention
    {
        dim3 grid(S_LEN / 128, BATCH * NH);
        attn_kernel<<<grid, 128>>>(qkv, attn);
    }
    // 3) Output projection + bias: [4096,1024] x [1024,1024]^T -> [4096,1024]
    {
        dim3 grid(DMODEL / 128, MROWS / 128);
        sgemm_nt_kernel<<<grid, 256>>>(attn, w_out, b_out, out,
                                       MROWS, DMODEL, DMODEL);
    }
}

// round 7
// speedup vs baseline: 2.3901x; 2.3901x over previous
#include <cuda_runtime.h>
#include <math.h>
#include <stdint.h>

// Problem constants
#define S_LEN 2048
#define BATCH 2
#define DMODEL 1024
#define NH 16
#define DKH 64
#define MROWS (S_LEN * BATCH)   // 4096

// Scratch (allocation-free rule: __device__ globals)
__device__ float g_qkv[(size_t)MROWS * 3 * DMODEL];   // [4096, 3072]
__device__ float g_attn[(size_t)MROWS * DMODEL];      // [4096, 1024]

// ---------------------------------------------------------------------------
// tf32 helpers
// ---------------------------------------------------------------------------
__device__ __forceinline__ float tf32r(float x) {
    uint32_t u;
    asm("cvt.rna.tf32.f32 %0, %1;" : "=r"(u) : "f"(x));
    return __uint_as_float(u);
}

// m16n8k8 tf32 mma, D (f32) += A (tf32,row) * B (tf32,col)
__device__ __forceinline__ void mma_tf32(float* d, const uint32_t* a, const uint32_t* b) {
    asm volatile(
        "mma.sync.aligned.m16n8k8.row.col.f32.tf32.tf32.f32 "
        "{%0,%1,%2,%3},{%4,%5,%6,%7},{%8,%9},{%0,%1,%2,%3};"
        : "+f"(d[0]), "+f"(d[1]), "+f"(d[2]), "+f"(d[3])
        : "r"(a[0]), "r"(a[1]), "r"(a[2]), "r"(a[3]), "r"(b[0]), "r"(b[1]));
}

// split x -> hi (tf32) + lo (tf32 of residual), residual exact in fp32
__device__ __forceinline__ void split_store4(float4 v, float* hp, float* lp) {
    float4 h, l;
    h.x = tf32r(v.x); l.x = tf32r(v.x - h.x);
    h.y = tf32r(v.y); l.y = tf32r(v.y - h.y);
    h.z = tf32r(v.z); l.z = tf32r(v.z - h.z);
    h.w = tf32r(v.w); l.w = tf32r(v.w - h.w);
    *(float4*)hp = h;
    *(float4*)lp = l;
}

__device__ __forceinline__ void split1(float v, uint32_t& hi, uint32_t& lo) {
    float h = tf32r(v);
    hi = __float_as_uint(h);
    lo = __float_as_uint(tf32r(v - h));
}

// ---------------------------------------------------------------------------
// 3xTF32 GEMM: C[m,n] = sum_k A[m,k]*B[n,k] (+bias[n])
// A row-major [M,K], B row-major [N,K], C row-major [M,N]
// BM=BN=128, BK=16, 256 threads = 8 warps (2x4), warp tile 64x32.
// ---------------------------------------------------------------------------
__global__ __launch_bounds__(256) void gemm_tf32_3x(
    const float* __restrict__ A, const float* __restrict__ B,
    const float* __restrict__ bias, float* __restrict__ C,
    int M, int N, int K)
{
    __shared__ float Ahs[128][20], Als[128][20], Bhs[128][20], Bls[128][20];

    const int tid  = threadIdx.x;
    const int lane = tid & 31;
    const int warp = tid >> 5;
    const int g    = lane >> 2;   // 0..7
    const int q4   = lane & 3;    // 0..3
    const int wm   = warp >> 2;   // 0..1
    const int wn   = warp & 3;    // 0..3
    const int mBase = blockIdx.y * 128;
    const int nBase = blockIdx.x * 128;

    float acc[4][4][4];
#pragma unroll
    for (int i = 0; i < 4; ++i)
#pragma unroll
        for (int j = 0; j < 4; ++j)
#pragma unroll
            for (int c = 0; c < 4; ++c) acc[i][j][c] = 0.f;

    const int lrow = tid >> 1;         // 0..127
    const int lk   = (tid & 1) << 3;   // 0 or 8
    const float* Ap = A + (size_t)(mBase + lrow) * K + lk;
    const float* Bp = B + (size_t)(nBase + lrow) * K + lk;

    for (int k0 = 0; k0 < K; k0 += 16) {
        float4 av0 = *(const float4*)(Ap + k0);
        float4 av1 = *(const float4*)(Ap + k0 + 4);
        float4 bv0 = *(const float4*)(Bp + k0);
        float4 bv1 = *(const float4*)(Bp + k0 + 4);
        __syncthreads();
        split_store4(av0, &Ahs[lrow][lk],     &Als[lrow][lk]);
        split_store4(av1, &Ahs[lrow][lk + 4], &Als[lrow][lk + 4]);
        split_store4(bv0, &Bhs[lrow][lk],     &Bls[lrow][lk]);
        split_store4(bv1, &Bhs[lrow][lk + 4], &Bls[lrow][lk + 4]);
        __syncthreads();

#pragma unroll
        for (int kc = 0; kc < 16; kc += 8) {
            uint32_t ah[4][4], al[4][4];
#pragma unroll
            for (int mf = 0; mf < 4; ++mf) {
                int r0 = wm * 64 + mf * 16 + g;
                int r1 = r0 + 8;
                ah[mf][0] = __float_as_uint(Ahs[r0][kc + q4]);
                ah[mf][1] = __float_as_uint(Ahs[r1][kc + q4]);
                ah[mf][2] = __float_as_uint(Ahs[r0][kc + 4 + q4]);
                ah[mf][3] = __float_as_uint(Ahs[r1][kc + 4 + q4]);
                al[mf][0] = __float_as_uint(Als[r0][kc + q4]);
                al[mf][1] = __float_as_uint(Als[r1][kc + q4]);
                al[mf][2] = __float_as_uint(Als[r0][kc + 4 + q4]);
                al[mf][3] = __float_as_uint(Als[r1][kc + 4 + q4]);
            }
            uint32_t bh[4][2], bl[4][2];
#pragma unroll
            for (int nf = 0; nf < 4; ++nf) {
                int c = wn * 32 + nf * 8 + g;
                bh[nf][0] = __float_as_uint(Bhs[c][kc + q4]);
                bh[nf][1] = __float_as_uint(Bhs[c][kc + 4 + q4]);
                bl[nf][0] = __float_as_uint(Bls[c][kc + q4]);
                bl[nf][1] = __float_as_uint(Bls[c][kc + 4 + q4]);
            }
#pragma unroll
            for (int mf = 0; mf < 4; ++mf)
#pragma unroll
                for (int nf = 0; nf < 4; ++nf) {
                    mma_tf32(acc[mf][nf], ah[mf], bh[nf]);
                    mma_tf32(acc[mf][nf], ah[mf], bl[nf]);
                    mma_tf32(acc[mf][nf], al[mf], bh[nf]);
                }
        }
    }

    // Epilogue
#pragma unroll
    for (int mf = 0; mf < 4; ++mf) {
        int r0 = mBase + wm * 64 + mf * 16 + g;
        int r1 = r0 + 8;
#pragma unroll
        for (int nf = 0; nf < 4; ++nf) {
            int col = nBase + wn * 32 + nf * 8 + 2 * q4;
            float bx = 0.f, by = 0.f;
            if (bias) { bx = bias[col]; by = bias[col + 1]; }
            *(float2*)(C + (size_t)r0 * N + col) =
                make_float2(acc[mf][nf][0] + bx, acc[mf][nf][1] + by);
            *(float2*)(C + (size_t)r1 * N + col) =
                make_float2(acc[mf][nf][2] + bx, acc[mf][nf][3] + by);
        }
    }
}

// ---------------------------------------------------------------------------
// Flash attention with 3xTF32 mma.
// grid: (S/64, B*H), block: 128 threads (4 warps, 16 query rows each).
// KV tile = 64 keys. Causal.
// smem layout (floats): Qs[64][68] | Kh[64][68] | Kl[64][68] |
//                       Vh[64][72] | Vl[64][72] | Ps[4][16][68]
// ---------------------------------------------------------------------------
#define QS_OFF 0
#define KH_OFF 4352
#define KL_OFF 8704
#define VH_OFF 13056
#define VL_OFF 17664
#define PS_OFF 22272
#define ATT_SMEM_FLOATS 26624
#define ATT_SMEM_BYTES (ATT_SMEM_FLOATS * 4)

__global__ __launch_bounds__(128) void attn_mma_kernel(
    const float* __restrict__ qkv, float* __restrict__ out)
{
    extern __shared__ float sm[];
    float* Qs = sm + QS_OFF;
    float* Kh = sm + KH_OFF;
    float* Kl = sm + KL_OFF;
    float* Vh = sm + VH_OFF;
    float* Vl = sm + VL_OFF;

    const int qt  = blockIdx.x;
    const int bh  = blockIdx.y;
    const int h   = bh & (NH - 1);
    const int b   = bh >> 4;
    const int tid = threadIdx.x;
    const int w    = tid >> 5;
    const int lane = tid & 31;
    const int g    = lane >> 2;
    const int q4   = lane & 3;
    float* Psw = sm + PS_OFF + w * (16 * 68);
    const int qBase = qt * 64;

    // Load Q tile (pre-scaled by 1/sqrt(dk)=0.125)
    for (int i = tid; i < 64 * 16; i += 128) {
        int r = i >> 4, c4 = (i & 15) << 2;
        const float* qp = qkv + ((size_t)((qBase + r) * BATCH + b)) * (3 * DMODEL)
                          + h * DKH + c4;
        float4 v = *(const float4*)qp;
        v.x *= 0.125f; v.y *= 0.125f; v.z *= 0.125f; v.w *= 0.125f;
        *(float4*)&Qs[r * 68 + c4] = v;
    }
    __syncthreads();

    // Q fragments (register-resident, hi/lo)
    uint32_t qh[8][4], ql[8][4];
    {
        int r0 = (w * 16 + g) * 68;
        int r1 = (w * 16 + g + 8) * 68;
#pragma unroll
        for (int kc = 0; kc < 8; ++kc) {
            split1(Qs[r0 + kc * 8 + q4],     qh[kc][0], ql[kc][0]);
            split1(Qs[r1 + kc * 8 + q4],     qh[kc][1], ql[kc][1]);
            split1(Qs[r0 + kc * 8 + 4 + q4], qh[kc][2], ql[kc][2]);
            split1(Qs[r1 + kc * 8 + 4 + q4], qh[kc][3], ql[kc][3]);
        }
    }

    float ofr[8][4];
#pragma unroll
    for (int nt = 0; nt < 8; ++nt)
#pragma unroll
        for (int c = 0; c < 4; ++c) ofr[nt][c] = 0.f;

    float m0 = -INFINITY, m1 = -INFINITY, l0 = 0.f, l1 = 0.f;
    const int qrow0 = qBase + w * 16 + g;
    const int qrow1 = qrow0 + 8;

    for (int kt = 0; kt <= qt; ++kt) {
        __syncthreads();
        // Load K/V tile, split hi/lo
        for (int i = tid; i < 64 * 16; i += 128) {
            int r = i >> 4, c4 = (i & 15) << 2;
            const float* kp = qkv + ((size_t)((kt * 64 + r) * BATCH + b)) * (3 * DMODEL)
                              + DMODEL + h * DKH + c4;
            float4 kv = *(const float4*)kp;
            float4 vv = *(const float4*)(kp + DMODEL);
            split_store4(kv, &Kh[r * 68 + c4], &Kl[r * 68 + c4]);
            split_store4(vv, &Vh[r * 72 + c4], &Vl[r * 72 + c4]);
        }
        __syncthreads();

        // S = Q K^T (3xTF32)
        float sfr[8][4];
#pragma unroll
        for (int nt = 0; nt < 8; ++nt)
#pragma unroll
            for (int c = 0; c < 4; ++c) sfr[nt][c] = 0.f;

#pragma unroll
        for (int kc = 0; kc < 8; ++kc) {
#pragma unroll
            for (int nt = 0; nt < 8; ++nt) {
                int base = (nt * 8 + g) * 68 + kc * 8 + q4;
                uint32_t bhv[2], blv[2];
                bhv[0] = __float_as_uint(Kh[base]);
                bhv[1] = __float_as_uint(Kh[base + 4]);
                blv[0] = __float_as_uint(Kl[base]);
                blv[1] = __float_as_uint(Kl[base + 4]);
                mma_tf32(sfr[nt], qh[kc], bhv);
                mma_tf32(sfr[nt], qh[kc], blv);
                mma_tf32(sfr[nt], ql[kc], bhv);
            }
        }

        // Causal mask (only the diagonal tile needs it)
        if (kt == qt) {
#pragma unroll
            for (int nt = 0; nt < 8; ++nt) {
                int key = kt * 64 + nt * 8 + 2 * q4;
                if (key     > qrow0) sfr[nt][0] = -INFINITY;
                if (key + 1 > qrow0) sfr[nt][1] = -INFINITY;
                if (key     > qrow1) sfr[nt][2] = -INFINITY;
                if (key + 1 > qrow1) sfr[nt][3] = -INFINITY;
            }
        }

        // Online softmax (rows g and g+8, owned by 4-lane groups)
        float mx0 = -INFINITY, mx1 = -INFINITY;
#pragma unroll
        for (int nt = 0; nt < 8; ++nt) {
            mx0 = fmaxf(mx0, fmaxf(sfr[nt][0], sfr[nt][1]));
            mx1 = fmaxf(mx1, fmaxf(sfr[nt][2], sfr[nt][3]));
        }
        mx0 = fmaxf(mx0, __shfl_xor_sync(0xffffffffu, mx0, 1));
        mx0 = fmaxf(mx0, __shfl_xor_sync(0xffffffffu, mx0, 2));
        mx1 = fmaxf(mx1, __shfl_xor_sync(0xffffffffu, mx1, 1));
        mx1 = fmaxf(mx1, __shfl_xor_sync(0xffffffffu, mx1, 2));

        float mn0 = fmaxf(m0, mx0), mn1 = fmaxf(m1, mx1);
        float cr0 = __expf(m0 - mn0), cr1 = __expf(m1 - mn1);
        l0 *= cr0; l1 *= cr1;
        m0 = mn0;  m1 = mn1;

        float ps0 = 0.f, ps1 = 0.f;
#pragma unroll
        for (int nt = 0; nt < 8; ++nt) {
            ofr[nt][0] *= cr0; ofr[nt][1] *= cr0;
            ofr[nt][2] *= cr1; ofr[nt][3] *= cr1;
            float p0 = __expf(sfr[nt][0] - m0);
            float p1 = __expf(sfr[nt][1] - m0);
            float p2 = __expf(sfr[nt][2] - m1);
            float p3 = __expf(sfr[nt][3] - m1);
            ps0 += p0 + p1; ps1 += p2 + p3;
            *(float2*)&Psw[g * 68 + nt * 8 + 2 * q4]       = make_float2(p0, p1);
            *(float2*)&Psw[(g + 8) * 68 + nt * 8 + 2 * q4] = make_float2(p2, p3);
        }
        ps0 += __shfl_xor_sync(0xffffffffu, ps0, 1);
        ps0 += __shfl_xor_sync(0xffffffffu, ps0, 2);
        ps1 += __shfl_xor_sync(0xffffffffu, ps1, 1);
        ps1 += __shfl_xor_sync(0xffffffffu, ps1, 2);
        l0 += ps0; l1 += ps1;
        __syncwarp();

        // O += P V (3xTF32)
#pragma unroll
        for (int kc = 0; kc < 8; ++kc) {
            uint32_t pah[4], pal[4];
            split1(Psw[g * 68 + kc * 8 + q4],           pah[0], pal[0]);
            split1(Psw[(g + 8) * 68 + kc * 8 + q4],     pah[1], pal[1]);
            split1(Psw[g * 68 + kc * 8 + 4 + q4],       pah[2], pal[2]);
            split1(Psw[(g + 8) * 68 + kc * 8 + 4 + q4], pah[3], pal[3]);
#pragma unroll
            for (int nt = 0; nt < 8; ++nt) {
                int base0 = (kc * 8 + q4) * 72 + nt * 8 + g;
                int base1 = (kc * 8 + 4 + q4) * 72 + nt * 8 + g;
                uint32_t bhv[2], blv[2];
                bhv[0] = __float_as_uint(Vh[base0]);
                bhv[1] = __float_as_uint(Vh[base1]);
                blv[0] = __float_as_uint(Vl[base0]);
                blv[1] = __float_as_uint(Vl[base1]);
                mma_tf32(ofr[nt], pah, bhv);
                mma_tf32(ofr[nt], pah, blv);
                mma_tf32(ofr[nt], pal, bhv);
            }
        }
    }

    // Epilogue: normalize and write
    float inv0 = 1.f / l0, inv1 = 1.f / l1;
    float* o0 = out + ((size_t)(qrow0 * BATCH + b)) * DMODEL + h * DKH;
    float* o1 = out + ((size_t)(qrow1 * BATCH + b)) * DMODEL + h * DKH;
#pragma unroll
    for (int nt = 0; nt < 8; ++nt) {
        int c = nt * 8 + 2 * q4;
        *(float2*)(o0 + c) = make_float2(ofr[nt][0] * inv0, ofr[nt][1] * inv0);
        *(float2*)(o1 + c) = make_float2(ofr[nt][2] * inv1, ofr[nt][3] * inv1);
    }
}

// ---------------------------------------------------------------------------
extern "C" void kernel_launch(void* const* d_in, const int* in_sizes, int n_in,
                              void* d_out, int out_size)
{
    const float* x     = (const float*)d_in[0];   // [S,B,D]
    const float* w_qkv = (const float*)d_in[1];   // [3D,D]
    const float* w_out = (const float*)d_in[2];   // [D,D]
    const float* b_out = (const float*)d_in[3];   // [D]
    float* out = (float*)d_out;

    float* qkv;  cudaGetSymbolAddress((void**)&qkv,  g_qkv);
    float* attn; cudaGetSymbolAddress((void**)&attn, g_attn);

    cudaFuncSetAttribute(attn_mma_kernel,
                         cudaFuncAttributeMaxDynamicSharedMemorySize,
                         ATT_SMEM_BYTES);

    // 1) QKV projection: [4096,1024] x [3072,1024]^T -> [4096,3072]
    gemm_tf32_3x<<<dim3(3 * DMODEL / 128, MROWS / 128), 256>>>(
        x, w_qkv, nullptr, qkv, MROWS, 3 * DMODEL, DMODEL);

    // 2) Causal flash attention (tensor core)
    attn_mma_kernel<<<dim3(S_LEN / 64, BATCH * NH), 128, ATT_SMEM_BYTES>>>(
        qkv, attn);

    // 3) Output projection + bias: [4096,1024] x [1024,1024]^T -> [4096,1024]
    gemm_tf32_3x<<<dim3(DMODEL / 128, MROWS / 128), 256>>>(
        attn, w_out, b_out, out, MROWS, DMODEL, DMODEL);
}

// round 10
// speedup vs baseline: 3.8270x; 1.6012x over previous
#include <cuda_runtime.h>
#include <cuda_bf16.h>
#include <math.h>
#include <stdint.h>

// Problem constants
#define S_LEN 2048
#define BATCH 2
#define DMODEL 1024
#define NH 16
#define DKH 64
#define MROWS (S_LEN * BATCH)   // 4096

// ---------------------------------------------------------------------------
// Scratch (allocation-free rule: __device__ globals). All split-bf16 pairs.
// ---------------------------------------------------------------------------
__device__ __nv_bfloat16 g_xh[(size_t)MROWS * DMODEL];
__device__ __nv_bfloat16 g_xl[(size_t)MROWS * DMODEL];
__device__ __nv_bfloat16 g_wqh[(size_t)3 * DMODEL * DMODEL];
__device__ __nv_bfloat16 g_wql[(size_t)3 * DMODEL * DMODEL];
__device__ __nv_bfloat16 g_woh[(size_t)DMODEL * DMODEL];
__device__ __nv_bfloat16 g_wol[(size_t)DMODEL * DMODEL];
__device__ __nv_bfloat16 g_qkvh[(size_t)MROWS * 3 * DMODEL];
__device__ __nv_bfloat16 g_qkvl[(size_t)MROWS * 3 * DMODEL];
__device__ __nv_bfloat16 g_vth[(size_t)BATCH * NH * DKH * S_LEN];  // [bh][d][s]
__device__ __nv_bfloat16 g_vtl[(size_t)BATCH * NH * DKH * S_LEN];
__device__ __nv_bfloat16 g_ah[(size_t)MROWS * DMODEL];
__device__ __nv_bfloat16 g_al[(size_t)MROWS * DMODEL];

// ---------------------------------------------------------------------------
// Helpers
// ---------------------------------------------------------------------------
__device__ __forceinline__ uint32_t smem_u32(const void* p) {
    uint32_t a;
    asm("{ .reg .u64 t; cvta.to.shared.u64 t, %1; cvt.u32.u64 %0, t; }"
        : "=r"(a) : "l"(p));
    return a;
}

// split (x,y) -> packed bf16x2 hi + packed bf16x2 lo
__device__ __forceinline__ void bsplit2(float x, float y, uint32_t& hi, uint32_t& lo) {
    __nv_bfloat16 hx = __float2bfloat16(x);
    __nv_bfloat16 hy = __float2bfloat16(y);
    __nv_bfloat16 lx = __float2bfloat16(x - __bfloat162float(hx));
    __nv_bfloat16 ly = __float2bfloat16(y - __bfloat162float(hy));
    hi = (uint32_t)__bfloat16_as_ushort(hx) | ((uint32_t)__bfloat16_as_ushort(hy) << 16);
    lo = (uint32_t)__bfloat16_as_ushort(lx) | ((uint32_t)__bfloat16_as_ushort(ly) << 16);
}

// m16n8k16 bf16 mma, D (f32) += A * B
__device__ __forceinline__ void mma_bf16(float* d, const uint32_t* a,
                                         uint32_t b0, uint32_t b1) {
    asm volatile(
        "mma.sync.aligned.m16n8k16.row.col.f32.bf16.bf16.f32 "
        "{%0,%1,%2,%3},{%4,%5,%6,%7},{%8,%9},{%0,%1,%2,%3};"
        : "+f"(d[0]), "+f"(d[1]), "+f"(d[2]), "+f"(d[3])
        : "r"(a[0]), "r"(a[1]), "r"(a[2]), "r"(a[3]), "r"(b0), "r"(b1));
}

__device__ __forceinline__ void cpasync16(uint32_t dst, const void* src) {
    asm volatile("cp.async.cg.shared.global [%0], [%1], 16;" :: "r"(dst), "l"(src));
}
__device__ __forceinline__ void cp_commit() {
    asm volatile("cp.async.commit_group;" ::: "memory");
}
template<int N> __device__ __forceinline__ void cp_wait() {
    asm volatile("cp.async.wait_group %0;" :: "n"(N) : "memory");
}

// ---------------------------------------------------------------------------
// Kernel: elementwise split fp32 -> bf16 hi/lo
// ---------------------------------------------------------------------------
__global__ __launch_bounds__(256) void split_kernel(
    const float* __restrict__ in, __nv_bfloat16* __restrict__ h,
    __nv_bfloat16* __restrict__ l, int n)
{
    int i4 = (blockIdx.x * 256 + threadIdx.x) * 4;
    if (i4 >= n) return;
    float4 v = *(const float4*)(in + i4);
    uint32_t h0, l0, h1, l1;
    bsplit2(v.x, v.y, h0, l0);
    bsplit2(v.z, v.w, h1, l1);
    *(uint2*)((char*)h + (size_t)i4 * 2) = make_uint2(h0, h1);
    *(uint2*)((char*)l + (size_t)i4 * 2) = make_uint2(l0, l1);
}

// ---------------------------------------------------------------------------
// bf16-split GEMM: C[m,n] = sum_k A[m,k]*B[n,k] (+bias)
// A,B pre-split bf16 (h,l). 3 products hh+hl+lh.
// BM=BN=128, BK=32, 256 threads (8 warps, 2x4, warp tile 64x32), 3-stage cp.async.
// Output: either fp32 Cf (+bias), or split pair (Ch,Cl) with cols<qscaleCols
// scaled by 0.125.
// smem/stage: Ah|Al|Bh|Bl, each 128 rows x 80B (32 bf16 data + pad) = 10240B.
// ---------------------------------------------------------------------------
#define G_STAGE_BYTES 40960
#define G_SMEM_BYTES (3 * G_STAGE_BYTES)   // 122880

__global__ __launch_bounds__(256, 1) void gemm_bf16x3(
    const __nv_bfloat16* __restrict__ Ah, const __nv_bfloat16* __restrict__ Al,
    const __nv_bfloat16* __restrict__ Bh, const __nv_bfloat16* __restrict__ Bl,
    const float* __restrict__ bias, float* __restrict__ Cf,
    __nv_bfloat16* __restrict__ Ch, __nv_bfloat16* __restrict__ Cl,
    int M, int N, int K, int qscaleCols)
{
    extern __shared__ char smem[];
    const uint32_t sbase = smem_u32(smem);
    const int tid  = threadIdx.x;
    const int lane = tid & 31;
    const int warp = tid >> 5;
    const int g    = lane >> 2;
    const int q4   = lane & 3;
    const int wm   = warp >> 2;
    const int wn   = warp & 3;
    const int mBase = blockIdx.y * 128;
    const int nBase = blockIdx.x * 128;

    float acc[4][4][4];
#pragma unroll
    for (int i = 0; i < 4; ++i)
#pragma unroll
        for (int j = 0; j < 4; ++j)
#pragma unroll
            for (int c = 0; c < 4; ++c) acc[i][j][c] = 0.f;

    // cp.async mapping
    const int mi  = tid >> 6;          // 0:Ah 1:Al 2:Bh 3:Bl
    const int sub = tid & 63;
    const __nv_bfloat16* srcbase = (mi == 0) ? Ah : (mi == 1) ? Al : (mi == 2) ? Bh : Bl;
    const int rbase = (mi < 2) ? mBase : nBase;

    const int NT = K / 32;

#define G_ISSUE(ITER) do {                                                     \
    int s_ = (ITER) % 3;                                                       \
    int k0_ = (ITER) * 32;                                                     \
    _Pragma("unroll")                                                          \
    for (int j_ = 0; j_ < 8; ++j_) {                                           \
        int cid_ = sub + j_ * 64;                                              \
        int row_ = cid_ >> 2, ch_ = cid_ & 3;                                  \
        const char* src_ = (const char*)(srcbase + (size_t)(rbase + row_) * K + k0_) + ch_ * 16; \
        uint32_t dst_ = sbase + s_ * G_STAGE_BYTES + mi * 10240 + row_ * 80 + ch_ * 16; \
        cpasync16(dst_, src_);                                                 \
    }                                                                          \
} while (0)

    G_ISSUE(0); cp_commit();
    G_ISSUE(1); cp_commit();

    for (int it = 0; it < NT; ++it) {
        if (it + 2 < NT)      { G_ISSUE(it + 2); cp_commit(); cp_wait<2>(); }
        else if (it + 1 < NT) { cp_wait<1>(); }
        else                  { cp_wait<0>(); }
        __syncthreads();

        const int s = it % 3;
        const uint32_t* SAh = (const uint32_t*)(smem + s * G_STAGE_BYTES);
        const uint32_t* SAl = SAh + 2560;
        const uint32_t* SBh = SAh + 5120;
        const uint32_t* SBl = SAh + 7680;

#pragma unroll
        for (int ks = 0; ks < 2; ++ks) {
            uint32_t ah[4][4], al[4][4];
#pragma unroll
            for (int mf = 0; mf < 4; ++mf) {
                int base = (wm * 64 + mf * 16 + g) * 20 + ks * 8 + q4;
                ah[mf][0] = SAh[base];       ah[mf][1] = SAh[base + 160];
                ah[mf][2] = SAh[base + 4];   ah[mf][3] = SAh[base + 164];
                al[mf][0] = SAl[base];       al[mf][1] = SAl[base + 160];
                al[mf][2] = SAl[base + 4];   al[mf][3] = SAl[base + 164];
            }
            uint32_t bh[4][2], bl[4][2];
#pragma unroll
            for (int nf = 0; nf < 4; ++nf) {
                int base = (wn * 32 + nf * 8 + g) * 20 + ks * 8 + q4;
                bh[nf][0] = SBh[base]; bh[nf][1] = SBh[base + 4];
                bl[nf][0] = SBl[base]; bl[nf][1] = SBl[base + 4];
            }
#pragma unroll
            for (int mf = 0; mf < 4; ++mf)
#pragma unroll
                for (int nf = 0; nf < 4; ++nf) {
                    mma_bf16(acc[mf][nf], ah[mf], bh[nf][0], bh[nf][1]);
                    mma_bf16(acc[mf][nf], ah[mf], bl[nf][0], bl[nf][1]);
                    mma_bf16(acc[mf][nf], al[mf], bh[nf][0], bh[nf][1]);
                }
        }
        __syncthreads();
    }
#undef G_ISSUE

    // Epilogue
    const int Np = N >> 1;
#pragma unroll
    for (int mf = 0; mf < 4; ++mf) {
        int r0 = mBase + wm * 64 + mf * 16 + g;
        int r1 = r0 + 8;
#pragma unroll
        for (int nf = 0; nf < 4; ++nf) {
            int col = nBase + wn * 32 + nf * 8 + 2 * q4;
            if (Cf) {
                float bx = bias ? bias[col] : 0.f;
                float by = bias ? bias[col + 1] : 0.f;
                *(float2*)(Cf + (size_t)r0 * N + col) =
                    make_float2(acc[mf][nf][0] + bx, acc[mf][nf][1] + by);
                *(float2*)(Cf + (size_t)r1 * N + col) =
                    make_float2(acc[mf][nf][2] + bx, acc[mf][nf][3] + by);
            } else {
                float sc = (col < qscaleCols) ? 0.125f : 1.f;
                uint32_t hi, lo;
                bsplit2(acc[mf][nf][0] * sc, acc[mf][nf][1] * sc, hi, lo);
                ((uint32_t*)Ch)[(size_t)r0 * Np + (col >> 1)] = hi;
                ((uint32_t*)Cl)[(size_t)r0 * Np + (col >> 1)] = lo;
                bsplit2(acc[mf][nf][2] * sc, acc[mf][nf][3] * sc, hi, lo);
                ((uint32_t*)Ch)[(size_t)r1 * Np + (col >> 1)] = hi;
                ((uint32_t*)Cl)[(size_t)r1 * Np + (col >> 1)] = lo;
            }
        }
    }
}

// ---------------------------------------------------------------------------
// Transpose V: QKV split (cols 2048+h*64..+63) -> Vt[bh][d][s]
// grid (S/64, B*H), 256 threads.
// ---------------------------------------------------------------------------
__global__ __launch_bounds__(256) void transpose_v_kernel(
    const __nv_bfloat16* __restrict__ QKVh, const __nv_bfloat16* __restrict__ QKVl,
    __nv_bfloat16* __restrict__ Vth, __nv_bfloat16* __restrict__ Vtl)
{
    __shared__ __nv_bfloat16 Th[64][72], Tl[64][72];
    const int sblk = blockIdx.x;
    const int bh   = blockIdx.y;
    const int b = bh >> 4, h = bh & 15;
    const int tid = threadIdx.x;

#pragma unroll
    for (int j = 0; j < 2; ++j) {
        int id = tid + j * 256;
        int row = id >> 3, ch = id & 7;
        size_t base = ((size_t)((sblk * 64 + row) * BATCH + b) * (3 * DMODEL)
                       + 2 * DMODEL + h * DKH);
        uint4 vh = *(const uint4*)((const char*)(QKVh + base) + ch * 16);
        uint4 vl = *(const uint4*)((const char*)(QKVl + base) + ch * 16);
        *(uint4*)((char*)&Th[row][0] + ch * 16) = vh;
        *(uint4*)((char*)&Tl[row][0] + ch * 16) = vl;
    }
    __syncthreads();

#pragma unroll
    for (int j = 0; j < 2; ++j) {
        int id = tid + j * 256;
        int d = id >> 3, ch = id & 7;
        int s0 = ch * 8;
        unsigned short ph[8], pl[8];
#pragma unroll
        for (int k = 0; k < 8; ++k) {
            ph[k] = __bfloat16_as_ushort(Th[s0 + k][d]);
            pl[k] = __bfloat16_as_ushort(Tl[s0 + k][d]);
        }
        size_t dstoff = (size_t)(bh * DKH + d) * S_LEN + sblk * 64 + s0;
        *(uint4*)(Vth + dstoff) = *(uint4*)ph;
        *(uint4*)(Vtl + dstoff) = *(uint4*)pl;
    }
}

// ---------------------------------------------------------------------------
// Flash attention, bf16-split mma (m16n8k16), 2-stage cp.async KV pipeline.
// grid (S/64, B*H), 128 threads (4 warps x 16 q rows). Q pre-scaled by 0.125.
// smem (u32 units): QH[64x36]=2304 | QL=2304 | PS 4 warps x (576 h + 576 l)
//                 | 2 stages x (KH,KL,VTH,VTL each 64x36=2304)
// ---------------------------------------------------------------------------
#define A_QH 0
#define A_QL 2304
#define A_PS 4608
#define A_ST 9216
#define A_STAGE_U32 9216
#define ATT_SMEM_BYTES ((A_ST + 2 * A_STAGE_U32) * 4)   // 110592

__global__ __launch_bounds__(128) void attn_bf16(
    const __nv_bfloat16* __restrict__ QKVh, const __nv_bfloat16* __restrict__ QKVl,
    const __nv_bfloat16* __restrict__ Vth, const __nv_bfloat16* __restrict__ Vtl,
    __nv_bfloat16* __restrict__ Oh, __nv_bfloat16* __restrict__ Ol)
{
    extern __shared__ uint32_t sm4[];
    const uint32_t sbase = smem_u32(sm4);
    const int qt  = blockIdx.x;
    const int bh  = blockIdx.y;
    const int h   = bh & 15;
    const int b   = bh >> 4;
    const int tid = threadIdx.x;
    const int w    = tid >> 5;
    const int lane = tid & 31;
    const int g    = lane >> 2;
    const int q4   = lane & 3;
    const int qBase = qt * 64;

    // Load Q tile (split, already scaled): 64 rows x 128B per array
#pragma unroll
    for (int j = 0; j < 4; ++j) {
        int id = tid + j * 128;
        int row = id >> 3, ch = id & 7;
        size_t src = (size_t)((qBase + row) * BATCH + b) * (3 * DMODEL) + h * DKH;
        uint4 vh = *(const uint4*)((const char*)(QKVh + src) + ch * 16);
        uint4 vl = *(const uint4*)((const char*)(QKVl + src) + ch * 16);
        *(uint4*)((char*)sm4 + row * 144 + ch * 16) = vh;
        *(uint4*)((char*)sm4 + A_QL * 4 + row * 144 + ch * 16) = vl;
    }
    __syncthreads();

    // Q fragments
    uint32_t qh[4][4], ql[4][4];
    {
        int r0 = (w * 16 + g) * 36;
        int r1 = r0 + 288;
#pragma unroll
        for (int kc = 0; kc < 4; ++kc) {
            qh[kc][0] = sm4[r0 + kc * 8 + q4];
            qh[kc][1] = sm4[r1 + kc * 8 + q4];
            qh[kc][2] = sm4[r0 + kc * 8 + 4 + q4];
            qh[kc][3] = sm4[r1 + kc * 8 + 4 + q4];
            ql[kc][0] = sm4[A_QL + r0 + kc * 8 + q4];
            ql[kc][1] = sm4[A_QL + r1 + kc * 8 + q4];
            ql[kc][2] = sm4[A_QL + r0 + kc * 8 + 4 + q4];
            ql[kc][3] = sm4[A_QL + r1 + kc * 8 + 4 + q4];
        }
    }

    float ofr[8][4];
#pragma unroll
    for (int nt = 0; nt < 8; ++nt)
#pragma unroll
        for (int c = 0; c < 4; ++c) ofr[nt][c] = 0.f;

    float m0 = -INFINITY, m1 = -INFINITY, l0 = 0.f, l1 = 0.f;
    const int qrow0 = qBase + w * 16 + g;
    const int qrow1 = qrow0 + 8;

    uint32_t* PH = sm4 + A_PS + w * 1152;
    uint32_t* PL = PH + 576;

#define KV_ISSUE(KT) do {                                                       \
    int s_ = (KT) & 1;                                                          \
    uint32_t stb_ = sbase + (A_ST + s_ * A_STAGE_U32) * 4;                      \
    _Pragma("unroll")                                                           \
    for (int j_ = 0; j_ < 4; ++j_) {                                            \
        int id_ = tid + j_ * 128;                                               \
        int row_ = id_ >> 3, ch_ = id_ & 7;                                     \
        size_t ks_ = (size_t)(((KT) * 64 + row_) * BATCH + b) * (3 * DMODEL)    \
                     + DMODEL + h * DKH;                                        \
        cpasync16(stb_ + row_ * 144 + ch_ * 16, (const char*)(QKVh + ks_) + ch_ * 16); \
        cpasync16(stb_ + 9216 + row_ * 144 + ch_ * 16, (const char*)(QKVl + ks_) + ch_ * 16); \
        size_t vs_ = (size_t)(bh * DKH + row_) * S_LEN + (KT) * 64;             \
        cpasync16(stb_ + 18432 + row_ * 144 + ch_ * 16, (const char*)(Vth + vs_) + ch_ * 16); \
        cpasync16(stb_ + 27648 + row_ * 144 + ch_ * 16, (const char*)(Vtl + vs_) + ch_ * 16); \
    }                                                                           \
} while (0)

    KV_ISSUE(0); cp_commit();

    for (int kt = 0; kt <= qt; ++kt) {
        if (kt < qt) { KV_ISSUE(kt + 1); cp_commit(); cp_wait<1>(); }
        else         { cp_wait<0>(); }
        __syncthreads();

        const int s = kt & 1;
        const uint32_t* KH = sm4 + A_ST + s * A_STAGE_U32;
        const uint32_t* KL = KH + 2304;
        const uint32_t* VH = KH + 4608;
        const uint32_t* VL = KH + 6912;

        // S = Q K^T
        float sfr[8][4];
#pragma unroll
        for (int nt = 0; nt < 8; ++nt)
#pragma unroll
            for (int c = 0; c < 4; ++c) sfr[nt][c] = 0.f;

#pragma unroll
        for (int kc = 0; kc < 4; ++kc) {
#pragma unroll
            for (int nt = 0; nt < 8; ++nt) {
                int base = (nt * 8 + g) * 36 + kc * 8 + q4;
                uint32_t b0h = KH[base], b1h = KH[base + 4];
                uint32_t b0l = KL[base], b1l = KL[base + 4];
                mma_bf16(sfr[nt], qh[kc], b0h, b1h);
                mma_bf16(sfr[nt], qh[kc], b0l, b1l);
                mma_bf16(sfr[nt], ql[kc], b0h, b1h);
            }
        }

        // Causal mask (diagonal tile only)
        if (kt == qt) {
#pragma unroll
            for (int nt = 0; nt < 8; ++nt) {
                int key = kt * 64 + nt * 8 + 2 * q4;
                if (key     > qrow0) sfr[nt][0] = -INFINITY;
                if (key + 1 > qrow0) sfr[nt][1] = -INFINITY;
                if (key     > qrow1) sfr[nt][2] = -INFINITY;
                if (key + 1 > qrow1) sfr[nt][3] = -INFINITY;
            }
        }

        // Online softmax
        float mx0 = -INFINITY, mx1 = -INFINITY;
#pragma unroll
        for (int nt = 0; nt < 8; ++nt) {
            mx0 = fmaxf(mx0, fmaxf(sfr[nt][0], sfr[nt][1]));
            mx1 = fmaxf(mx1, fmaxf(sfr[nt][2], sfr[nt][3]));
        }
        mx0 = fmaxf(mx0, __shfl_xor_sync(0xffffffffu, mx0, 1));
        mx0 = fmaxf(mx0, __shfl_xor_sync(0xffffffffu, mx0, 2));
        mx1 = fmaxf(mx1, __shfl_xor_sync(0xffffffffu, mx1, 1));
        mx1 = fmaxf(mx1, __shfl_xor_sync(0xffffffffu, mx1, 2));

        float mn0 = fmaxf(m0, mx0), mn1 = fmaxf(m1, mx1);
        float cr0 = __expf(m0 - mn0), cr1 = __expf(m1 - mn1);
        l0 *= cr0; l1 *= cr1;
        m0 = mn0;  m1 = mn1;

        float ps0 = 0.f, ps1 = 0.f;
#pragma unroll
        for (int nt = 0; nt < 8; ++nt) {
            ofr[nt][0] *= cr0; ofr[nt][1] *= cr0;
            ofr[nt][2] *= cr1; ofr[nt][3] *= cr1;
            float p0 = __expf(sfr[nt][0] - m0);
            float p1 = __expf(sfr[nt][1] - m0);
            float p2 = __expf(sfr[nt][2] - m1);
            float p3 = __expf(sfr[nt][3] - m1);
            ps0 += p0 + p1; ps1 += p2 + p3;
            uint32_t hi, lo;
            bsplit2(p0, p1, hi, lo);
            PH[g * 36 + nt * 4 + q4] = hi;
            PL[g * 36 + nt * 4 + q4] = lo;
            bsplit2(p2, p3, hi, lo);
            PH[(g + 8) * 36 + nt * 4 + q4] = hi;
            PL[(g + 8) * 36 + nt * 4 + q4] = lo;
        }
        ps0 += __shfl_xor_sync(0xffffffffu, ps0, 1);
        ps0 += __shfl_xor_sync(0xffffffffu, ps0, 2);
        ps1 += __shfl_xor_sync(0xffffffffu, ps1, 1);
        ps1 += __shfl_xor_sync(0xffffffffu, ps1, 2);
        l0 += ps0; l1 += ps1;
        __syncwarp();

        // O += P V   (V^T tiles: rows = dims, k = keys)
#pragma unroll
        for (int kc = 0; kc < 4; ++kc) {
            uint32_t pah[4], pal[4];
            pah[0] = PH[g * 36 + kc * 8 + q4];
            pah[1] = PH[(g + 8) * 36 + kc * 8 + q4];
            pah[2] = PH[g * 36 + kc * 8 + 4 + q4];
            pah[3] = PH[(g + 8) * 36 + kc * 8 + 4 + q4];
            pal[0] = PL[g * 36 + kc * 8 + q4];
            pal[1] = PL[(g + 8) * 36 + kc * 8 + q4];
            pal[2] = PL[g * 36 + kc * 8 + 4 + q4];
            pal[3] = PL[(g + 8) * 36 + kc * 8 + 4 + q4];
#pragma unroll
            for (int nt = 0; nt < 8; ++nt) {
                int base = (nt * 8 + g) * 36 + kc * 8 + q4;
                uint32_t b0h = VH[base], b1h = VH[base + 4];
                uint32_t b0l = VL[base], b1l = VL[base + 4];
                mma_bf16(ofr[nt], pah, b0h, b1h);
                mma_bf16(ofr[nt], pah, b0l, b1l);
                mma_bf16(ofr[nt], pal, b0h, b1h);
            }
        }
        __syncthreads();
    }
#undef KV_ISSUE

    // Epilogue: normalize, split-write attention output
    float inv0 = 1.f / l0, inv1 = 1.f / l1;
    size_t row0 = (size_t)(qrow0 * BATCH + b) * (DMODEL / 2);
    size_t row1 = (size_t)(qrow1 * BATCH + b) * (DMODEL / 2);
#pragma unroll
    for (int nt = 0; nt < 8; ++nt) {
        int pcol = h * 32 + nt * 4 + q4;
        uint32_t hi, lo;
        bsplit2(ofr[nt][0] * inv0, ofr[nt][1] * inv0, hi, lo);
        ((uint32_t*)Oh)[row0 + pcol] = hi;
        ((uint32_t*)Ol)[row0 + pcol] = lo;
        bsplit2(ofr[nt][2] * inv1, ofr[nt][3] * inv1, hi, lo);
        ((uint32_t*)Oh)[row1 + pcol] = hi;
        ((uint32_t*)Ol)[row1 + pcol] = lo;
    }
}

// ---------------------------------------------------------------------------
extern "C" void kernel_launch(void* const* d_in, const int* in_sizes, int n_in,
                              void* d_out, int out_size)
{
    const float* x     = (const float*)d_in[0];   // [S,B,D]
    const float* w_qkv = (const float*)d_in[1];   // [3D,D]
    const float* w_out = (const float*)d_in[2];   // [D,D]
    const float* b_out = (const float*)d_in[3];   // [D]
    float* out = (float*)d_out;

    __nv_bfloat16 *xh, *xl, *wqh, *wql, *woh, *wol, *qkvh, *qkvl, *vth, *vtl, *ah, *al;
    cudaGetSymbolAddress((void**)&xh,   g_xh);
    cudaGetSymbolAddress((void**)&xl,   g_xl);
    cudaGetSymbolAddress((void**)&wqh,  g_wqh);
    cudaGetSymbolAddress((void**)&wql,  g_wql);
    cudaGetSymbolAddress((void**)&woh,  g_woh);
    cudaGetSymbolAddress((void**)&wol,  g_wol);
    cudaGetSymbolAddress((void**)&qkvh, g_qkvh);
    cudaGetSymbolAddress((void**)&qkvl, g_qkvl);
    cudaGetSymbolAddress((void**)&vth,  g_vth);
    cudaGetSymbolAddress((void**)&vtl,  g_vtl);
    cudaGetSymbolAddress((void**)&ah,   g_ah);
    cudaGetSymbolAddress((void**)&al,   g_al);

    cudaFuncSetAttribute(gemm_bf16x3,
                         cudaFuncAttributeMaxDynamicSharedMemorySize, G_SMEM_BYTES);
    cudaFuncSetAttribute(attn_bf16,
                         cudaFuncAttributeMaxDynamicSharedMemorySize, ATT_SMEM_BYTES);

    // 0) Split inputs to bf16 hi/lo
    {
        int n1 = MROWS * DMODEL;        // x
        int n2 = 3 * DMODEL * DMODEL;   // w_qkv
        int n3 = DMODEL * DMODEL;       // w_out
        split_kernel<<<(n1 / 4 + 255) / 256, 256>>>(x, xh, xl, n1);
        split_kernel<<<(n2 / 4 + 255) / 256, 256>>>(w_qkv, wqh, wql, n2);
        split_kernel<<<(n3 / 4 + 255) / 256, 256>>>(w_out, woh, wol, n3);
    }

    // 1) QKV projection -> split qkv (Q cols scaled by 0.125)
    gemm_bf16x3<<<dim3(3 * DMODEL / 128, MROWS / 128), 256, G_SMEM_BYTES>>>(
        xh, xl, wqh, wql, nullptr, nullptr, qkvh, qkvl,
        MROWS, 3 * DMODEL, DMODEL, DMODEL);

    // 2) Transpose V per (b,h): [s][d] -> [bh][d][s]
    transpose_v_kernel<<<dim3(S_LEN / 64, BATCH * NH), 256>>>(qkvh, qkvl, vth, vtl);

    // 3) Causal flash attention -> split attention output
    attn_bf16<<<dim3(S_LEN / 64, BATCH * NH), 128, ATT_SMEM_BYTES>>>(
        qkvh, qkvl, vth, vtl, ah, al);

    // 4) Output projection + bias -> fp32 out
    gemm_bf16x3<<<dim3(DMODEL / 128, MROWS / 128), 256, G_SMEM_BYTES>>>(
        ah, al, woh, wol, b_out, out, nullptr, nullptr,
        MROWS, DMODEL, DMODEL, 0);
}

// round 11
// speedup vs baseline: 4.3619x; 1.1398x over previous
#include <cuda_runtime.h>
#include <cuda_bf16.h>
#include <math.h>
#include <stdint.h>

// Problem constants
#define S_LEN 2048
#define BATCH 2
#define DMODEL 1024
#define NH 16
#define DKH 64
#define MROWS (S_LEN * BATCH)   // 4096

// ---------------------------------------------------------------------------
// Scratch (allocation-free rule: __device__ globals). All split-bf16 pairs.
// ---------------------------------------------------------------------------
__device__ __nv_bfloat16 g_xh[(size_t)MROWS * DMODEL];
__device__ __nv_bfloat16 g_xl[(size_t)MROWS * DMODEL];
__device__ __nv_bfloat16 g_wqh[(size_t)3 * DMODEL * DMODEL];
__device__ __nv_bfloat16 g_wql[(size_t)3 * DMODEL * DMODEL];
__device__ __nv_bfloat16 g_woh[(size_t)DMODEL * DMODEL];
__device__ __nv_bfloat16 g_wol[(size_t)DMODEL * DMODEL];
__device__ __nv_bfloat16 g_qkvh[(size_t)MROWS * 3 * DMODEL];
__device__ __nv_bfloat16 g_qkvl[(size_t)MROWS * 3 * DMODEL];
__device__ __nv_bfloat16 g_vth[(size_t)BATCH * NH * DKH * S_LEN];  // [bh][d][s]
__device__ __nv_bfloat16 g_vtl[(size_t)BATCH * NH * DKH * S_LEN];
__device__ __nv_bfloat16 g_ah[(size_t)MROWS * DMODEL];
__device__ __nv_bfloat16 g_al[(size_t)MROWS * DMODEL];

// ---------------------------------------------------------------------------
// Helpers
// ---------------------------------------------------------------------------
__device__ __forceinline__ uint32_t smem_u32(const void* p) {
    uint32_t a;
    asm("{ .reg .u64 t; cvta.to.shared.u64 t, %1; cvt.u32.u64 %0, t; }"
        : "=r"(a) : "l"(p));
    return a;
}

// split (x,y) -> packed bf16x2 hi + packed bf16x2 lo
__device__ __forceinline__ void bsplit2(float x, float y, uint32_t& hi, uint32_t& lo) {
    __nv_bfloat16 hx = __float2bfloat16(x);
    __nv_bfloat16 hy = __float2bfloat16(y);
    __nv_bfloat16 lx = __float2bfloat16(x - __bfloat162float(hx));
    __nv_bfloat16 ly = __float2bfloat16(y - __bfloat162float(hy));
    hi = (uint32_t)__bfloat16_as_ushort(hx) | ((uint32_t)__bfloat16_as_ushort(hy) << 16);
    lo = (uint32_t)__bfloat16_as_ushort(lx) | ((uint32_t)__bfloat16_as_ushort(ly) << 16);
}

// m16n8k16 bf16 mma, D (f32) += A * B
__device__ __forceinline__ void mma_bf16(float* d, const uint32_t* a,
                                         uint32_t b0, uint32_t b1) {
    asm volatile(
        "mma.sync.aligned.m16n8k16.row.col.f32.bf16.bf16.f32 "
        "{%0,%1,%2,%3},{%4,%5,%6,%7},{%8,%9},{%0,%1,%2,%3};"
        : "+f"(d[0]), "+f"(d[1]), "+f"(d[2]), "+f"(d[3])
        : "r"(a[0]), "r"(a[1]), "r"(a[2]), "r"(a[3]), "r"(b0), "r"(b1));
}

__device__ __forceinline__ void ldm_x4(uint32_t* r, uint32_t addr) {
    asm volatile(
        "ldmatrix.sync.aligned.m8n8.x4.shared.b16 {%0,%1,%2,%3}, [%4];"
        : "=r"(r[0]), "=r"(r[1]), "=r"(r[2]), "=r"(r[3]) : "r"(addr));
}

__device__ __forceinline__ void cpasync16(uint32_t dst, const void* src) {
    asm volatile("cp.async.cg.shared.global [%0], [%1], 16;" :: "r"(dst), "l"(src));
}
__device__ __forceinline__ void cp_commit() {
    asm volatile("cp.async.commit_group;" ::: "memory");
}
template<int N> __device__ __forceinline__ void cp_wait() {
    asm volatile("cp.async.wait_group %0;" :: "n"(N) : "memory");
}

// ---------------------------------------------------------------------------
// Kernel: elementwise split fp32 -> bf16 hi/lo
// ---------------------------------------------------------------------------
__global__ __launch_bounds__(256) void split_kernel(
    const float* __restrict__ in, __nv_bfloat16* __restrict__ h,
    __nv_bfloat16* __restrict__ l, int n)
{
    int i4 = (blockIdx.x * 256 + threadIdx.x) * 4;
    if (i4 >= n) return;
    float4 v = *(const float4*)(in + i4);
    uint32_t h0, l0, h1, l1;
    bsplit2(v.x, v.y, h0, l0);
    bsplit2(v.z, v.w, h1, l1);
    *(uint2*)((char*)h + (size_t)i4 * 2) = make_uint2(h0, h1);
    *(uint2*)((char*)l + (size_t)i4 * 2) = make_uint2(l0, l1);
}

// ---------------------------------------------------------------------------
// bf16-split GEMM: C[m,n] = sum_k A[m,k]*B[n,k] (+bias)
// BM=128, BN=64, BK=32, 128 threads (4 warps, 2x2, warp tile 64x32).
// 3-stage cp.async, ldmatrix fragment loads. 2 CTAs/SM (smem 90KB).
// Rows in smem: 32 bf16 (64B) + 16B pad = 80B stride (ldmatrix conflict-free).
// Stage: Ah@0 (10240) | Al@10240 | Bh@20480 (5120) | Bl@25600.  30720B/stage.
// ---------------------------------------------------------------------------
#define G_STAGE_BYTES 30720
#define G_SMEM_BYTES (3 * G_STAGE_BYTES)   // 92160

__global__ __launch_bounds__(128, 2) void gemm_bf16x3(
    const __nv_bfloat16* __restrict__ Ah, const __nv_bfloat16* __restrict__ Al,
    const __nv_bfloat16* __restrict__ Bh, const __nv_bfloat16* __restrict__ Bl,
    const float* __restrict__ bias, float* __restrict__ Cf,
    __nv_bfloat16* __restrict__ Ch, __nv_bfloat16* __restrict__ Cl,
    int M, int N, int K, int qscaleCols)
{
    extern __shared__ char smem[];
    const uint32_t sbase = smem_u32(smem);
    const int tid  = threadIdx.x;
    const int lane = tid & 31;
    const int warp = tid >> 5;
    const int g    = lane >> 2;
    const int q4   = lane & 3;
    const int wm   = warp >> 1;       // 0..1 (64 rows each)
    const int wn   = warp & 1;        // 0..1 (32 cols each)
    const int mBase = blockIdx.y * 128;
    const int nBase = blockIdx.x * 64;

    float acc[4][4][4];
#pragma unroll
    for (int i = 0; i < 4; ++i)
#pragma unroll
        for (int j = 0; j < 4; ++j)
#pragma unroll
            for (int c = 0; c < 4; ++c) acc[i][j][c] = 0.f;

    // ldmatrix per-lane base addresses (within stage 0)
    // A: matrices j = lane>>3: row = wm*64 + (j&1)*8 + (lane&7), kbyte = (j>>1)*16
    const int lj = lane >> 3, l7 = lane & 7;
    const uint32_t aRowBase = (uint32_t)(wm * 64 + (lj & 1) * 8 + l7) * 80
                              + (uint32_t)(lj >> 1) * 16;
    // B: per np: row = wn*32 + np*16 + (j>>1)*8 + (l&7), kbyte = (j&1)*16
    const uint32_t bRowBase = (uint32_t)(wn * 32 + (lj >> 1) * 8 + l7) * 80
                              + (uint32_t)(lj & 1) * 16;

    const int NT = K / 32;

#define G_ISSUE(ITER) do {                                                      \
    int s_ = (ITER) % 3;                                                        \
    int k0_ = (ITER) * 32;                                                      \
    uint32_t stb_ = sbase + s_ * G_STAGE_BYTES;                                 \
    _Pragma("unroll")                                                           \
    for (int j_ = 0; j_ < 4; ++j_) {  /* Ah then Al */                          \
        int cid_ = tid + j_ * 128;                                              \
        int row_ = cid_ >> 2, ch_ = cid_ & 3;                                   \
        cpasync16(stb_ + row_ * 80 + ch_ * 16,                                  \
                  (const char*)(Ah + (size_t)(mBase + row_) * K + k0_) + ch_ * 16); \
        cpasync16(stb_ + 10240 + row_ * 80 + ch_ * 16,                          \
                  (const char*)(Al + (size_t)(mBase + row_) * K + k0_) + ch_ * 16); \
    }                                                                           \
    _Pragma("unroll")                                                           \
    for (int j_ = 0; j_ < 2; ++j_) {  /* Bh then Bl */                          \
        int cid_ = tid + j_ * 128;                                              \
        int row_ = cid_ >> 2, ch_ = cid_ & 3;                                   \
        cpasync16(stb_ + 20480 + row_ * 80 + ch_ * 16,                          \
                  (const char*)(Bh + (size_t)(nBase + row_) * K + k0_) + ch_ * 16); \
        cpasync16(stb_ + 25600 + row_ * 80 + ch_ * 16,                          \
                  (const char*)(Bl + (size_t)(nBase + row_) * K + k0_) + ch_ * 16); \
    }                                                                           \
} while (0)

    G_ISSUE(0); cp_commit();
    G_ISSUE(1); cp_commit();

    for (int it = 0; it < NT; ++it) {
        if (it + 2 < NT)      { G_ISSUE(it + 2); cp_commit(); cp_wait<2>(); }
        else if (it + 1 < NT) { cp_wait<1>(); }
        else                  { cp_wait<0>(); }
        __syncthreads();

        const uint32_t stb = sbase + (it % 3) * G_STAGE_BYTES;

#pragma unroll
        for (int ks = 0; ks < 2; ++ks) {
            const uint32_t kk = ks * 32;
            uint32_t ah[4][4], al[4][4];
#pragma unroll
            for (int mf = 0; mf < 4; ++mf) {
                ldm_x4(ah[mf], stb + aRowBase + mf * (16 * 80) + kk);
                ldm_x4(al[mf], stb + 10240 + aRowBase + mf * (16 * 80) + kk);
            }
            uint32_t bh[4][2], bl[4][2];
#pragma unroll
            for (int np = 0; np < 2; ++np) {
                uint32_t r[4];
                ldm_x4(r, stb + 20480 + bRowBase + np * (16 * 80) + kk);
                bh[np * 2][0] = r[0]; bh[np * 2][1] = r[1];
                bh[np * 2 + 1][0] = r[2]; bh[np * 2 + 1][1] = r[3];
                ldm_x4(r, stb + 25600 + bRowBase + np * (16 * 80) + kk);
                bl[np * 2][0] = r[0]; bl[np * 2][1] = r[1];
                bl[np * 2 + 1][0] = r[2]; bl[np * 2 + 1][1] = r[3];
            }
#pragma unroll
            for (int mf = 0; mf < 4; ++mf)
#pragma unroll
                for (int nf = 0; nf < 4; ++nf) {
                    mma_bf16(acc[mf][nf], ah[mf], bh[nf][0], bh[nf][1]);
                    mma_bf16(acc[mf][nf], ah[mf], bl[nf][0], bl[nf][1]);
                    mma_bf16(acc[mf][nf], al[mf], bh[nf][0], bh[nf][1]);
                }
        }
        __syncthreads();
    }
#undef G_ISSUE

    // Epilogue
    const int Np = N >> 1;
#pragma unroll
    for (int mf = 0; mf < 4; ++mf) {
        int r0 = mBase + wm * 64 + mf * 16 + g;
        int r1 = r0 + 8;
#pragma unroll
        for (int nf = 0; nf < 4; ++nf) {
            int col = nBase + wn * 32 + nf * 8 + 2 * q4;
            if (Cf) {
                float bx = bias ? bias[col] : 0.f;
                float by = bias ? bias[col + 1] : 0.f;
                *(float2*)(Cf + (size_t)r0 * N + col) =
                    make_float2(acc[mf][nf][0] + bx, acc[mf][nf][1] + by);
                *(float2*)(Cf + (size_t)r1 * N + col) =
                    make_float2(acc[mf][nf][2] + bx, acc[mf][nf][3] + by);
            } else {
                float sc = (col < qscaleCols) ? 0.125f : 1.f;
                uint32_t hi, lo;
                bsplit2(acc[mf][nf][0] * sc, acc[mf][nf][1] * sc, hi, lo);
                ((uint32_t*)Ch)[(size_t)r0 * Np + (col >> 1)] = hi;
                ((uint32_t*)Cl)[(size_t)r0 * Np + (col >> 1)] = lo;
                bsplit2(acc[mf][nf][2] * sc, acc[mf][nf][3] * sc, hi, lo);
                ((uint32_t*)Ch)[(size_t)r1 * Np + (col >> 1)] = hi;
                ((uint32_t*)Cl)[(size_t)r1 * Np + (col >> 1)] = lo;
            }
        }
    }
}

// ---------------------------------------------------------------------------
// Transpose V: QKV split (cols 2048+h*64..+63) -> Vt[bh][d][s]
// grid (S/64, B*H), 256 threads.
// ---------------------------------------------------------------------------
__global__ __launch_bounds__(256) void transpose_v_kernel(
    const __nv_bfloat16* __restrict__ QKVh, const __nv_bfloat16* __restrict__ QKVl,
    __nv_bfloat16* __restrict__ Vth, __nv_bfloat16* __restrict__ Vtl)
{
    __shared__ __nv_bfloat16 Th[64][72], Tl[64][72];
    const int sblk = blockIdx.x;
    const int bh   = blockIdx.y;
    const int b = bh >> 4, h = bh & 15;
    const int tid = threadIdx.x;

#pragma unroll
    for (int j = 0; j < 2; ++j) {
        int id = tid + j * 256;
        int row = id >> 3, ch = id & 7;
        size_t base = ((size_t)((sblk * 64 + row) * BATCH + b) * (3 * DMODEL)
                       + 2 * DMODEL + h * DKH);
        uint4 vh = *(const uint4*)((const char*)(QKVh + base) + ch * 16);
        uint4 vl = *(const uint4*)((const char*)(QKVl + base) + ch * 16);
        *(uint4*)((char*)&Th[row][0] + ch * 16) = vh;
        *(uint4*)((char*)&Tl[row][0] + ch * 16) = vl;
    }
    __syncthreads();

#pragma unroll
    for (int j = 0; j < 2; ++j) {
        int id = tid + j * 256;
        int d = id >> 3, ch = id & 7;
        int s0 = ch * 8;
        unsigned short ph[8], pl[8];
#pragma unroll
        for (int k = 0; k < 8; ++k) {
            ph[k] = __bfloat16_as_ushort(Th[s0 + k][d]);
            pl[k] = __bfloat16_as_ushort(Tl[s0 + k][d]);
        }
        size_t dstoff = (size_t)(bh * DKH + d) * S_LEN + sblk * 64 + s0;
        *(uint4*)(Vth + dstoff) = *(uint4*)ph;
        *(uint4*)(Vtl + dstoff) = *(uint4*)pl;
    }
}

// ---------------------------------------------------------------------------
// Flash attention, bf16-split mma (m16n8k16), 2-stage cp.async KV pipeline.
// grid (S/64, B*H), 128 threads (4 warps x 16 q rows). Q pre-scaled by 0.125.
// qt processed in DESCENDING order (heavy tiles launch first).
// ---------------------------------------------------------------------------
#define A_QH 0
#define A_QL 2304
#define A_PS 4608
#define A_ST 9216
#define A_STAGE_U32 9216
#define ATT_SMEM_BYTES ((A_ST + 2 * A_STAGE_U32) * 4)   // 110592

__global__ __launch_bounds__(128) void attn_bf16(
    const __nv_bfloat16* __restrict__ QKVh, const __nv_bfloat16* __restrict__ QKVl,
    const __nv_bfloat16* __restrict__ Vth, const __nv_bfloat16* __restrict__ Vtl,
    __nv_bfloat16* __restrict__ Oh, __nv_bfloat16* __restrict__ Ol)
{
    extern __shared__ uint32_t sm4[];
    const uint32_t sbase = smem_u32(sm4);
    const int qt  = gridDim.x - 1 - blockIdx.x;   // heavy tiles first
    const int bh  = blockIdx.y;
    const int h   = bh & 15;
    const int b   = bh >> 4;
    const int tid = threadIdx.x;
    const int w    = tid >> 5;
    const int lane = tid & 31;
    const int g    = lane >> 2;
    const int q4   = lane & 3;
    const int qBase = qt * 64;

    // Load Q tile (split, already scaled): 64 rows x 128B per array
#pragma unroll
    for (int j = 0; j < 4; ++j) {
        int id = tid + j * 128;
        int row = id >> 3, ch = id & 7;
        size_t src = (size_t)((qBase + row) * BATCH + b) * (3 * DMODEL) + h * DKH;
        uint4 vh = *(const uint4*)((const char*)(QKVh + src) + ch * 16);
        uint4 vl = *(const uint4*)((const char*)(QKVl + src) + ch * 16);
        *(uint4*)((char*)sm4 + row * 144 + ch * 16) = vh;
        *(uint4*)((char*)sm4 + A_QL * 4 + row * 144 + ch * 16) = vl;
    }
    __syncthreads();

    // Q fragments
    uint32_t qh[4][4], ql[4][4];
    {
        int r0 = (w * 16 + g) * 36;
        int r1 = r0 + 288;
#pragma unroll
        for (int kc = 0; kc < 4; ++kc) {
            qh[kc][0] = sm4[r0 + kc * 8 + q4];
            qh[kc][1] = sm4[r1 + kc * 8 + q4];
            qh[kc][2] = sm4[r0 + kc * 8 + 4 + q4];
            qh[kc][3] = sm4[r1 + kc * 8 + 4 + q4];
            ql[kc][0] = sm4[A_QL + r0 + kc * 8 + q4];
            ql[kc][1] = sm4[A_QL + r1 + kc * 8 + q4];
            ql[kc][2] = sm4[A_QL + r0 + kc * 8 + 4 + q4];
            ql[kc][3] = sm4[A_QL + r1 + kc * 8 + 4 + q4];
        }
    }

    float ofr[8][4];
#pragma unroll
    for (int nt = 0; nt < 8; ++nt)
#pragma unroll
        for (int c = 0; c < 4; ++c) ofr[nt][c] = 0.f;

    float m0 = -INFINITY, m1 = -INFINITY, l0 = 0.f, l1 = 0.f;
    const int qrow0 = qBase + w * 16 + g;
    const int qrow1 = qrow0 + 8;

    uint32_t* PH = sm4 + A_PS + w * 1152;
    uint32_t* PL = PH + 576;

#define KV_ISSUE(KT) do {                                                       \
    int s_ = (KT) & 1;                                                          \
    uint32_t stb_ = sbase + (A_ST + s_ * A_STAGE_U32) * 4;                      \
    _Pragma("unroll")                                                           \
    for (int j_ = 0; j_ < 4; ++j_) {                                            \
        int id_ = tid + j_ * 128;                                               \
        int row_ = id_ >> 3, ch_ = id_ & 7;                                     \
        size_t ks_ = (size_t)(((KT) * 64 + row_) * BATCH + b) * (3 * DMODEL)    \
                     + DMODEL + h * DKH;                                        \
        cpasync16(stb_ + row_ * 144 + ch_ * 16, (const char*)(QKVh + ks_) + ch_ * 16); \
        cpasync16(stb_ + 9216 + row_ * 144 + ch_ * 16, (const char*)(QKVl + ks_) + ch_ * 16); \
        size_t vs_ = (size_t)(bh * DKH + row_) * S_LEN + (KT) * 64;             \
        cpasync16(stb_ + 18432 + row_ * 144 + ch_ * 16, (const char*)(Vth + vs_) + ch_ * 16); \
        cpasync16(stb_ + 27648 + row_ * 144 + ch_ * 16, (const char*)(Vtl + vs_) + ch_ * 16); \
    }                                                                           \
} while (0)

    KV_ISSUE(0); cp_commit();

    for (int kt = 0; kt <= qt; ++kt) {
        if (kt < qt) { KV_ISSUE(kt + 1); cp_commit(); cp_wait<1>(); }
        else         { cp_wait<0>(); }
        __syncthreads();

        const int s = kt & 1;
        const uint32_t* KH = sm4 + A_ST + s * A_STAGE_U32;
        const uint32_t* KL = KH + 2304;
        const uint32_t* VH = KH + 4608;
        const uint32_t* VL = KH + 6912;

        // S = Q K^T
        float sfr[8][4];
#pragma unroll
        for (int nt = 0; nt < 8; ++nt)
#pragma unroll
            for (int c = 0; c < 4; ++c) sfr[nt][c] = 0.f;

#pragma unroll
        for (int kc = 0; kc < 4; ++kc) {
#pragma unroll
            for (int nt = 0; nt < 8; ++nt) {
                int base = (nt * 8 + g) * 36 + kc * 8 + q4;
                uint32_t b0h = KH[base], b1h = KH[base + 4];
                uint32_t b0l = KL[base], b1l = KL[base + 4];
                mma_bf16(sfr[nt], qh[kc], b0h, b1h);
                mma_bf16(sfr[nt], qh[kc], b0l, b1l);
                mma_bf16(sfr[nt], ql[kc], b0h, b1h);
            }
        }

        // Causal mask (diagonal tile only)
        if (kt == qt) {
#pragma unroll
            for (int nt = 0; nt < 8; ++nt) {
                int key = kt * 64 + nt * 8 + 2 * q4;
                if (key     > qrow0) sfr[nt][0] = -INFINITY;
                if (key + 1 > qrow0) sfr[nt][1] = -INFINITY;
                if (key     > qrow1) sfr[nt][2] = -INFINITY;
                if (key + 1 > qrow1) sfr[nt][3] = -INFINITY;
            }
        }

        // Online softmax
        float mx0 = -INFINITY, mx1 = -INFINITY;
#pragma unroll
        for (int nt = 0; nt < 8; ++nt) {
            mx0 = fmaxf(mx0, fmaxf(sfr[nt][0], sfr[nt][1]));
            mx1 = fmaxf(mx1, fmaxf(sfr[nt][2], sfr[nt][3]));
        }
        mx0 = fmaxf(mx0, __shfl_xor_sync(0xffffffffu, mx0, 1));
        mx0 = fmaxf(mx0, __shfl_xor_sync(0xffffffffu, mx0, 2));
        mx1 = fmaxf(mx1, __shfl_xor_sync(0xffffffffu, mx1, 1));
        mx1 = fmaxf(mx1, __shfl_xor_sync(0xffffffffu, mx1, 2));

        float mn0 = fmaxf(m0, mx0), mn1 = fmaxf(m1, mx1);
        float cr0 = __expf(m0 - mn0), cr1 = __expf(m1 - mn1);
        l0 *= cr0; l1 *= cr1;
        m0 = mn0;  m1 = mn1;

        float ps0 = 0.f, ps1 = 0.f;
#pragma unroll
        for (int nt = 0; nt < 8; ++nt) {
            ofr[nt][0] *= cr0; ofr[nt][1] *= cr0;
            ofr[nt][2] *= cr1; ofr[nt][3] *= cr1;
            float p0 = __expf(sfr[nt][0] - m0);
            float p1 = __expf(sfr[nt][1] - m0);
            float p2 = __expf(sfr[nt][2] - m1);
            float p3 = __expf(sfr[nt][3] - m1);
            ps0 += p0 + p1; ps1 += p2 + p3;
            uint32_t hi, lo;
            bsplit2(p0, p1, hi, lo);
            PH[g * 36 + nt * 4 + q4] = hi;
            PL[g * 36 + nt * 4 + q4] = lo;
            bsplit2(p2, p3, hi, lo);
            PH[(g + 8) * 36 + nt * 4 + q4] = hi;
            PL[(g + 8) * 36 + nt * 4 + q4] = lo;
        }
        ps0 += __shfl_xor_sync(0xffffffffu, ps0, 1);
        ps0 += __shfl_xor_sync(0xffffffffu, ps0, 2);
        ps1 += __shfl_xor_sync(0xffffffffu, ps1, 1);
        ps1 += __shfl_xor_sync(0xffffffffu, ps1, 2);
        l0 += ps0; l1 += ps1;
        __syncwarp();

        // O += P V   (V^T tiles: rows = dims, k = keys)
#pragma unroll
        for (int kc = 0; kc < 4; ++kc) {
            uint32_t pah[4], pal[4];
            pah[0] = PH[g * 36 + kc * 8 + q4];
            pah[1] = PH[(g + 8) * 36 + kc * 8 + q4];
            pah[2] = PH[g * 36 + kc * 8 + 4 + q4];
            pah[3] = PH[(g + 8) * 36 + kc * 8 + 4 + q4];
            pal[0] = PL[g * 36 + kc * 8 + q4];
            pal[1] = PL[(g + 8) * 36 + kc * 8 + q4];
            pal[2] = PL[g * 36 + kc * 8 + 4 + q4];
            pal[3] = PL[(g + 8) * 36 + kc * 8 + 4 + q4];
#pragma unroll
            for (int nt = 0; nt < 8; ++nt) {
                int base = (nt * 8 + g) * 36 + kc * 8 + q4;
                uint32_t b0h = VH[base], b1h = VH[base + 4];
                uint32_t b0l = VL[base], b1l = VL[base + 4];
                mma_bf16(ofr[nt], pah, b0h, b1h);
                mma_bf16(ofr[nt], pah, b0l, b1l);
                mma_bf16(ofr[nt], pal, b0h, b1h);
            }
        }
        __syncthreads();
    }
#undef KV_ISSUE

    // Epilogue: normalize, split-write attention output
    float inv0 = 1.f / l0, inv1 = 1.f / l1;
    size_t row0 = (size_t)(qrow0 * BATCH + b) * (DMODEL / 2);
    size_t row1 = (size_t)(qrow1 * BATCH + b) * (DMODEL / 2);
#pragma unroll
    for (int nt = 0; nt < 8; ++nt) {
        int pcol = h * 32 + nt * 4 + q4;
        uint32_t hi, lo;
        bsplit2(ofr[nt][0] * inv0, ofr[nt][1] * inv0, hi, lo);
        ((uint32_t*)Oh)[row0 + pcol] = hi;
        ((uint32_t*)Ol)[row0 + pcol] = lo;
        bsplit2(ofr[nt][2] * inv1, ofr[nt][3] * inv1, hi, lo);
        ((uint32_t*)Oh)[row1 + pcol] = hi;
        ((uint32_t*)Ol)[row1 + pcol] = lo;
    }
}

// ---------------------------------------------------------------------------
extern "C" void kernel_launch(void* const* d_in, const int* in_sizes, int n_in,
                              void* d_out, int out_size)
{
    const float* x     = (const float*)d_in[0];   // [S,B,D]
    const float* w_qkv = (const float*)d_in[1];   // [3D,D]
    const float* w_out = (const float*)d_in[2];   // [D,D]
    const float* b_out = (const float*)d_in[3];   // [D]
    float* out = (float*)d_out;

    __nv_bfloat16 *xh, *xl, *wqh, *wql, *woh, *wol, *qkvh, *qkvl, *vth, *vtl, *ah, *al;
    cudaGetSymbolAddress((void**)&xh,   g_xh);
    cudaGetSymbolAddress((void**)&xl,   g_xl);
    cudaGetSymbolAddress((void**)&wqh,  g_wqh);
    cudaGetSymbolAddress((void**)&wql,  g_wql);
    cudaGetSymbolAddress((void**)&woh,  g_woh);
    cudaGetSymbolAddress((void**)&wol,  g_wol);
    cudaGetSymbolAddress((void**)&qkvh, g_qkvh);
    cudaGetSymbolAddress((void**)&qkvl, g_qkvl);
    cudaGetSymbolAddress((void**)&vth,  g_vth);
    cudaGetSymbolAddress((void**)&vtl,  g_vtl);
    cudaGetSymbolAddress((void**)&ah,   g_ah);
    cudaGetSymbolAddress((void**)&al,   g_al);

    cudaFuncSetAttribute(gemm_bf16x3,
                         cudaFuncAttributeMaxDynamicSharedMemorySize, G_SMEM_BYTES);
    cudaFuncSetAttribute(attn_bf16,
                         cudaFuncAttributeMaxDynamicSharedMemorySize, ATT_SMEM_BYTES);

    // 0) Split inputs to bf16 hi/lo
    {
        int n1 = MROWS * DMODEL;        // x
        int n2 = 3 * DMODEL * DMODEL;   // w_qkv
        int n3 = DMODEL * DMODEL;       // w_out
        split_kernel<<<(n1 / 4 + 255) / 256, 256>>>(x, xh, xl, n1);
        split_kernel<<<(n2 / 4 + 255) / 256, 256>>>(w_qkv, wqh, wql, n2);
        split_kernel<<<(n3 / 4 + 255) / 256, 256>>>(w_out, woh, wol, n3);
    }

    // 1) QKV projection -> split qkv (Q cols scaled by 0.125)
    gemm_bf16x3<<<dim3(3 * DMODEL / 64, MROWS / 128), 128, G_SMEM_BYTES>>>(
        xh, xl, wqh, wql, nullptr, nullptr, qkvh, qkvl,
        MROWS, 3 * DMODEL, DMODEL, DMODEL);

    // 2) Transpose V per (b,h): [s][d] -> [bh][d][s]
    transpose_v_kernel<<<dim3(S_LEN / 64, BATCH * NH), 256>>>(qkvh, qkvl, vth, vtl);

    // 3) Causal flash attention -> split attention output
    attn_bf16<<<dim3(S_LEN / 64, BATCH * NH), 128, ATT_SMEM_BYTES>>>(
        qkvh, qkvl, vth, vtl, ah, al);

    // 4) Output projection + bias -> fp32 out
    gemm_bf16x3<<<dim3(DMODEL / 64, MROWS / 128), 128, G_SMEM_BYTES>>>(
        ah, al, woh, wol, b_out, out, nullptr, nullptr,
        MROWS, DMODEL, DMODEL, 0);
}

// round 13
// speedup vs baseline: 4.7445x; 1.0877x over previous
#include <cuda_runtime.h>
#include <cuda_bf16.h>
#include <math.h>
#include <stdint.h>

// Problem constants
#define S_LEN 2048
#define BATCH 2
#define DMODEL 1024
#define NH 16
#define DKH 64
#define MROWS (S_LEN * BATCH)   // 4096

// ---------------------------------------------------------------------------
// Scratch (allocation-free rule: __device__ globals). All split-bf16 pairs.
// ---------------------------------------------------------------------------
__device__ __nv_bfloat16 g_xh[(size_t)MROWS * DMODEL];
__device__ __nv_bfloat16 g_xl[(size_t)MROWS * DMODEL];
__device__ __nv_bfloat16 g_wqh[(size_t)3 * DMODEL * DMODEL];
__device__ __nv_bfloat16 g_wql[(size_t)3 * DMODEL * DMODEL];
__device__ __nv_bfloat16 g_woh[(size_t)DMODEL * DMODEL];
__device__ __nv_bfloat16 g_wol[(size_t)DMODEL * DMODEL];
__device__ __nv_bfloat16 g_qkvh[(size_t)MROWS * 3 * DMODEL];
__device__ __nv_bfloat16 g_qkvl[(size_t)MROWS * 3 * DMODEL];
__device__ __nv_bfloat16 g_ah[(size_t)MROWS * DMODEL];
__device__ __nv_bfloat16 g_al[(size_t)MROWS * DMODEL];

// ---------------------------------------------------------------------------
// Helpers
// ---------------------------------------------------------------------------
__device__ __forceinline__ uint32_t smem_u32(const void* p) {
    uint32_t a;
    asm("{ .reg .u64 t; cvta.to.shared.u64 t, %1; cvt.u32.u64 %0, t; }"
        : "=r"(a) : "l"(p));
    return a;
}

// split (x,y) -> packed bf16x2 hi + packed bf16x2 lo
__device__ __forceinline__ void bsplit2(float x, float y, uint32_t& hi, uint32_t& lo) {
    __nv_bfloat16 hx = __float2bfloat16(x);
    __nv_bfloat16 hy = __float2bfloat16(y);
    __nv_bfloat16 lx = __float2bfloat16(x - __bfloat162float(hx));
    __nv_bfloat16 ly = __float2bfloat16(y - __bfloat162float(hy));
    hi = (uint32_t)__bfloat16_as_ushort(hx) | ((uint32_t)__bfloat16_as_ushort(hy) << 16);
    lo = (uint32_t)__bfloat16_as_ushort(lx) | ((uint32_t)__bfloat16_as_ushort(ly) << 16);
}

// m16n8k16 bf16 mma, D (f32) += A * B
__device__ __forceinline__ void mma_bf16(float* d, const uint32_t* a,
                                         uint32_t b0, uint32_t b1) {
    asm volatile(
        "mma.sync.aligned.m16n8k16.row.col.f32.bf16.bf16.f32 "
        "{%0,%1,%2,%3},{%4,%5,%6,%7},{%8,%9},{%0,%1,%2,%3};"
        : "+f"(d[0]), "+f"(d[1]), "+f"(d[2]), "+f"(d[3])
        : "r"(a[0]), "r"(a[1]), "r"(a[2]), "r"(a[3]), "r"(b0), "r"(b1));
}

__device__ __forceinline__ void ldm_x4(uint32_t* r, uint32_t addr) {
    asm volatile(
        "ldmatrix.sync.aligned.m8n8.x4.shared.b16 {%0,%1,%2,%3}, [%4];"
        : "=r"(r[0]), "=r"(r[1]), "=r"(r[2]), "=r"(r[3]) : "r"(addr));
}
__device__ __forceinline__ void ldm_x2(uint32_t* r, uint32_t addr) {
    asm volatile(
        "ldmatrix.sync.aligned.m8n8.x2.shared.b16 {%0,%1}, [%2];"
        : "=r"(r[0]), "=r"(r[1]) : "r"(addr));
}
__device__ __forceinline__ void ldm_x2t(uint32_t* r, uint32_t addr) {
    asm volatile(
        "ldmatrix.sync.aligned.m8n8.x2.trans.shared.b16 {%0,%1}, [%2];"
        : "=r"(r[0]), "=r"(r[1]) : "r"(addr));
}

__device__ __forceinline__ void cpasync16(uint32_t dst, const void* src) {
    asm volatile("cp.async.cg.shared.global [%0], [%1], 16;" :: "r"(dst), "l"(src));
}
__device__ __forceinline__ void cp_commit() {
    asm volatile("cp.async.commit_group;" ::: "memory");
}
template<int N> __device__ __forceinline__ void cp_wait() {
    asm volatile("cp.async.wait_group %0;" :: "n"(N) : "memory");
}

// ---------------------------------------------------------------------------
// Kernel: elementwise split fp32 -> bf16 hi/lo
// ---------------------------------------------------------------------------
__global__ __launch_bounds__(256) void split_kernel(
    const float* __restrict__ in, __nv_bfloat16* __restrict__ h,
    __nv_bfloat16* __restrict__ l, int n)
{
    int i4 = (blockIdx.x * 256 + threadIdx.x) * 4;
    if (i4 >= n) return;
    float4 v = *(const float4*)(in + i4);
    uint32_t h0, l0, h1, l1;
    bsplit2(v.x, v.y, h0, l0);
    bsplit2(v.z, v.w, h1, l1);
    *(uint2*)((char*)h + (size_t)i4 * 2) = make_uint2(h0, h1);
    *(uint2*)((char*)l + (size_t)i4 * 2) = make_uint2(l0, l1);
}

// ---------------------------------------------------------------------------
// bf16-split GEMM: C[m,n] = sum_k A[m,k]*B[n,k] (+bias)
// BM=128, BN=64, BK=32, 128 threads (4 warps, 2x2, warp tile 64x32).
// 3-stage cp.async, ldmatrix fragment loads, ONE sync per iter,
// split terms de-chained (hh sweep, hl sweep, lh sweep).
// ---------------------------------------------------------------------------
#define G_STAGE_BYTES 30720
#define G_SMEM_BYTES (3 * G_STAGE_BYTES)   // 92160

__global__ __launch_bounds__(128, 2) void gemm_bf16x3(
    const __nv_bfloat16* __restrict__ Ah, const __nv_bfloat16* __restrict__ Al,
    const __nv_bfloat16* __restrict__ Bh, const __nv_bfloat16* __restrict__ Bl,
    const float* __restrict__ bias, float* __restrict__ Cf,
    __nv_bfloat16* __restrict__ Ch, __nv_bfloat16* __restrict__ Cl,
    int M, int N, int K, int qscaleCols)
{
    extern __shared__ char smem[];
    const uint32_t sbase = smem_u32(smem);
    const int tid  = threadIdx.x;
    const int lane = tid & 31;
    const int warp = tid >> 5;
    const int g    = lane >> 2;
    const int q4   = lane & 3;
    const int wm   = warp >> 1;       // 0..1 (64 rows each)
    const int wn   = warp & 1;        // 0..1 (32 cols each)
    const int mBase = blockIdx.y * 128;
    const int nBase = blockIdx.x * 64;

    float acc[4][4][4];
#pragma unroll
    for (int i = 0; i < 4; ++i)
#pragma unroll
        for (int j = 0; j < 4; ++j)
#pragma unroll
            for (int c = 0; c < 4; ++c) acc[i][j][c] = 0.f;

    const int lj = lane >> 3, l7 = lane & 7;
    const uint32_t aRowBase = (uint32_t)(wm * 64 + (lj & 1) * 8 + l7) * 80
                              + (uint32_t)(lj >> 1) * 16;
    const uint32_t bRowBase = (uint32_t)(wn * 32 + (lj >> 1) * 8 + l7) * 80
                              + (uint32_t)(lj & 1) * 16;

    const int NT = K / 32;

#define G_ISSUE(ITER) do {                                                      \
    int s_ = (ITER) % 3;                                                        \
    int k0_ = (ITER) * 32;                                                      \
    uint32_t stb_ = sbase + s_ * G_STAGE_BYTES;                                 \
    _Pragma("unroll")                                                           \
    for (int j_ = 0; j_ < 4; ++j_) {  /* Ah then Al */                          \
        int cid_ = tid + j_ * 128;                                              \
        int row_ = cid_ >> 2, ch_ = cid_ & 3;                                   \
        cpasync16(stb_ + row_ * 80 + ch_ * 16,                                  \
                  (const char*)(Ah + (size_t)(mBase + row_) * K + k0_) + ch_ * 16); \
        cpasync16(stb_ + 10240 + row_ * 80 + ch_ * 16,                          \
                  (const char*)(Al + (size_t)(mBase + row_) * K + k0_) + ch_ * 16); \
    }                                                                           \
    _Pragma("unroll")                                                           \
    for (int j_ = 0; j_ < 2; ++j_) {  /* Bh then Bl */                          \
        int cid_ = tid + j_ * 128;                                              \
        int row_ = cid_ >> 2, ch_ = cid_ & 3;                                   \
        cpasync16(stb_ + 20480 + row_ * 80 + ch_ * 16,                          \
                  (const char*)(Bh + (size_t)(nBase + row_) * K + k0_) + ch_ * 16); \
        cpasync16(stb_ + 25600 + row_ * 80 + ch_ * 16,                          \
                  (const char*)(Bl + (size_t)(nBase + row_) * K + k0_) + ch_ * 16); \
    }                                                                           \
} while (0)

    G_ISSUE(0); cp_commit();
    G_ISSUE(1); cp_commit();

    for (int it = 0; it < NT; ++it) {
        if (it + 1 < NT) cp_wait<1>(); else cp_wait<0>();
        __syncthreads();
        if (it + 2 < NT) { G_ISSUE(it + 2); cp_commit(); }

        const uint32_t stb = sbase + (it % 3) * G_STAGE_BYTES;

#pragma unroll
        for (int ks = 0; ks < 2; ++ks) {
            const uint32_t kk = ks * 32;
            uint32_t ah[4][4], al[4][4];
#pragma unroll
            for (int mf = 0; mf < 4; ++mf) {
                ldm_x4(ah[mf], stb + aRowBase + mf * (16 * 80) + kk);
                ldm_x4(al[mf], stb + 10240 + aRowBase + mf * (16 * 80) + kk);
            }
            uint32_t bh[4][2], bl[4][2];
#pragma unroll
            for (int np = 0; np < 2; ++np) {
                uint32_t r[4];
                ldm_x4(r, stb + 20480 + bRowBase + np * (16 * 80) + kk);
                bh[np * 2][0] = r[0]; bh[np * 2][1] = r[1];
                bh[np * 2 + 1][0] = r[2]; bh[np * 2 + 1][1] = r[3];
                ldm_x4(r, stb + 25600 + bRowBase + np * (16 * 80) + kk);
                bl[np * 2][0] = r[0]; bl[np * 2][1] = r[1];
                bl[np * 2 + 1][0] = r[2]; bl[np * 2 + 1][1] = r[3];
            }
            // de-chained 3-term sweeps (acc reuse distance = 16 mmas)
#pragma unroll
            for (int mf = 0; mf < 4; ++mf)
#pragma unroll
                for (int nf = 0; nf < 4; ++nf)
                    mma_bf16(acc[mf][nf], ah[mf], bh[nf][0], bh[nf][1]);
#pragma unroll
            for (int mf = 0; mf < 4; ++mf)
#pragma unroll
                for (int nf = 0; nf < 4; ++nf)
                    mma_bf16(acc[mf][nf], ah[mf], bl[nf][0], bl[nf][1]);
#pragma unroll
            for (int mf = 0; mf < 4; ++mf)
#pragma unroll
                for (int nf = 0; nf < 4; ++nf)
                    mma_bf16(acc[mf][nf], al[mf], bh[nf][0], bh[nf][1]);
        }
    }
#undef G_ISSUE

    // Epilogue
    const int Np = N >> 1;
#pragma unroll
    for (int mf = 0; mf < 4; ++mf) {
        int r0 = mBase + wm * 64 + mf * 16 + g;
        int r1 = r0 + 8;
#pragma unroll
        for (int nf = 0; nf < 4; ++nf) {
            int col = nBase + wn * 32 + nf * 8 + 2 * q4;
            if (Cf) {
                float bx = bias ? bias[col] : 0.f;
                float by = bias ? bias[col + 1] : 0.f;
                *(float2*)(Cf + (size_t)r0 * N + col) =
                    make_float2(acc[mf][nf][0] + bx, acc[mf][nf][1] + by);
                *(float2*)(Cf + (size_t)r1 * N + col) =
                    make_float2(acc[mf][nf][2] + bx, acc[mf][nf][3] + by);
            } else {
                float sc = (col < qscaleCols) ? 0.125f : 1.f;
                uint32_t hi, lo;
                bsplit2(acc[mf][nf][0] * sc, acc[mf][nf][1] * sc, hi, lo);
                ((uint32_t*)Ch)[(size_t)r0 * Np + (col >> 1)] = hi;
                ((uint32_t*)Cl)[(size_t)r0 * Np + (col >> 1)] = lo;
                bsplit2(acc[mf][nf][2] * sc, acc[mf][nf][3] * sc, hi, lo);
                ((uint32_t*)Ch)[(size_t)r1 * Np + (col >> 1)] = hi;
                ((uint32_t*)Cl)[(size_t)r1 * Np + (col >> 1)] = lo;
            }
        }
    }
}

// ---------------------------------------------------------------------------
// Flash attention, bf16-split mma (m16n8k16), 2-stage cp.async KV pipeline.
// grid (S/64, B*H), 128 threads (4 warps x 16 q rows). Q pre-scaled by 0.125.
// qt DESCENDING. P stays in registers (fragment layout == exp output layout).
// K fragments: ldmatrix.x2 (non-trans). V fragments: ldmatrix.x2.trans on
// K-major V rows (no pre-transpose kernel). One __syncthreads per KV tile.
// smem (u32): QH[64x36] | QL | 2 stages x (KH,KL,VH,VL each 64x36)
// ---------------------------------------------------------------------------
#define A_QL 2304
#define A_ST 4608
#define A_STAGE_U32 9216
#define ATT_SMEM_BYTES ((A_ST + 2 * A_STAGE_U32) * 4)   // 92160

__global__ __launch_bounds__(128) void attn_bf16(
    const __nv_bfloat16* __restrict__ QKVh, const __nv_bfloat16* __restrict__ QKVl,
    __nv_bfloat16* __restrict__ Oh, __nv_bfloat16* __restrict__ Ol)
{
    extern __shared__ uint32_t sm4[];
    const uint32_t sbase = smem_u32(sm4);
    const int qt  = gridDim.x - 1 - blockIdx.x;   // heavy tiles first
    const int bh  = blockIdx.y;
    const int h   = bh & 15;
    const int b   = bh >> 4;
    const int tid = threadIdx.x;
    const int w    = tid >> 5;
    const int lane = tid & 31;
    const int g    = lane >> 2;
    const int q4   = lane & 3;
    const int qBase = qt * 64;

#define KV_ISSUE(KT) do {                                                       \
    int s_ = (KT) & 1;                                                          \
    uint32_t stb_ = sbase + (A_ST + s_ * A_STAGE_U32) * 4;                      \
    _Pragma("unroll")                                                           \
    for (int j_ = 0; j_ < 4; ++j_) {                                            \
        int id_ = tid + j_ * 128;                                               \
        int row_ = id_ >> 3, ch_ = id_ & 7;                                     \
        size_t ks_ = (size_t)(((KT) * 64 + row_) * BATCH + b) * (3 * DMODEL)    \
                     + DMODEL + h * DKH;                                        \
        size_t vs_ = ks_ + DMODEL;                                              \
        cpasync16(stb_ + row_ * 144 + ch_ * 16, (const char*)(QKVh + ks_) + ch_ * 16); \
        cpasync16(stb_ + 9216 + row_ * 144 + ch_ * 16, (const char*)(QKVl + ks_) + ch_ * 16); \
        cpasync16(stb_ + 18432 + row_ * 144 + ch_ * 16, (const char*)(QKVh + vs_) + ch_ * 16); \
        cpasync16(stb_ + 27648 + row_ * 144 + ch_ * 16, (const char*)(QKVl + vs_) + ch_ * 16); \
    }                                                                           \
} while (0)

    KV_ISSUE(0); cp_commit();

    // Load Q tile (split, already scaled): 64 rows x 128B per array
#pragma unroll
    for (int j = 0; j < 4; ++j) {
        int id = tid + j * 128;
        int row = id >> 3, ch = id & 7;
        size_t src = (size_t)((qBase + row) * BATCH + b) * (3 * DMODEL) + h * DKH;
        uint4 vh = *(const uint4*)((const char*)(QKVh + src) + ch * 16);
        uint4 vl = *(const uint4*)((const char*)(QKVl + src) + ch * 16);
        *(uint4*)((char*)sm4 + row * 144 + ch * 16) = vh;
        *(uint4*)((char*)sm4 + A_QL * 4 + row * 144 + ch * 16) = vl;
    }
    __syncthreads();

    // Q fragments
    uint32_t qh[4][4], ql[4][4];
    {
        int r0 = (w * 16 + g) * 36;
        int r1 = r0 + 288;
#pragma unroll
        for (int kc = 0; kc < 4; ++kc) {
            qh[kc][0] = sm4[r0 + kc * 8 + q4];
            qh[kc][1] = sm4[r1 + kc * 8 + q4];
            qh[kc][2] = sm4[r0 + kc * 8 + 4 + q4];
            qh[kc][3] = sm4[r1 + kc * 8 + 4 + q4];
            ql[kc][0] = sm4[A_QL + r0 + kc * 8 + q4];
            ql[kc][1] = sm4[A_QL + r1 + kc * 8 + q4];
            ql[kc][2] = sm4[A_QL + r0 + kc * 8 + 4 + q4];
            ql[kc][3] = sm4[A_QL + r1 + kc * 8 + 4 + q4];
        }
    }

    float ofr[8][4];
#pragma unroll
    for (int nt = 0; nt < 8; ++nt)
#pragma unroll
        for (int c = 0; c < 4; ++c) ofr[nt][c] = 0.f;

    float m0 = -INFINITY, m1 = -INFINITY, l0 = 0.f, l1 = 0.f;
    const int qrow0 = qBase + w * 16 + g;
    const int qrow1 = qrow0 + 8;

    // ldmatrix per-lane address terms
    const int l7  = lane & 7;
    const int l15 = lane & 15;
    const uint32_t kLane = (uint32_t)l7 * 144 + (uint32_t)((lane >> 3) & 1) * 16;
    const uint32_t vLane = (uint32_t)l15 * 144;

    for (int kt = 0; kt <= qt; ++kt) {
        cp_wait<0>();
        __syncthreads();
        if (kt < qt) { KV_ISSUE(kt + 1); cp_commit(); }

        const uint32_t stb = sbase + (A_ST + (kt & 1) * A_STAGE_U32) * 4;
        const uint32_t stbKH = stb + kLane;
        const uint32_t stbKL = stbKH + 9216;
        const uint32_t stbVH = stb + 18432 + vLane;
        const uint32_t stbVL = stbVH + 9216;

        // S = Q K^T (3 de-chained sweeps per kc)
        float sfr[8][4];
#pragma unroll
        for (int nt = 0; nt < 8; ++nt)
#pragma unroll
            for (int c = 0; c < 4; ++c) sfr[nt][c] = 0.f;

#pragma unroll
        for (int kc = 0; kc < 4; ++kc) {
            uint32_t kh2[8][2], kl2[8][2];
#pragma unroll
            for (int nt = 0; nt < 8; ++nt) {
                ldm_x2(kh2[nt], stbKH + nt * (8 * 144) + kc * 32);
                ldm_x2(kl2[nt], stbKL + nt * (8 * 144) + kc * 32);
            }
#pragma unroll
            for (int nt = 0; nt < 8; ++nt)
                mma_bf16(sfr[nt], qh[kc], kh2[nt][0], kh2[nt][1]);
#pragma unroll
            for (int nt = 0; nt < 8; ++nt)
                mma_bf16(sfr[nt], qh[kc], kl2[nt][0], kl2[nt][1]);
#pragma unroll
            for (int nt = 0; nt < 8; ++nt)
                mma_bf16(sfr[nt], ql[kc], kh2[nt][0], kh2[nt][1]);
        }

        // Causal mask (diagonal tile only)
        if (kt == qt) {
#pragma unroll
            for (int nt = 0; nt < 8; ++nt) {
                int key = kt * 64 + nt * 8 + 2 * q4;
                if (key     > qrow0) sfr[nt][0] = -INFINITY;
                if (key + 1 > qrow0) sfr[nt][1] = -INFINITY;
                if (key     > qrow1) sfr[nt][2] = -INFINITY;
                if (key + 1 > qrow1) sfr[nt][3] = -INFINITY;
            }
        }

        // Online softmax
        float mx0 = -INFINITY, mx1 = -INFINITY;
#pragma unroll
        for (int nt = 0; nt < 8; ++nt) {
            mx0 = fmaxf(mx0, fmaxf(sfr[nt][0], sfr[nt][1]));
            mx1 = fmaxf(mx1, fmaxf(sfr[nt][2], sfr[nt][3]));
        }
        mx0 = fmaxf(mx0, __shfl_xor_sync(0xffffffffu, mx0, 1));
        mx0 = fmaxf(mx0, __shfl_xor_sync(0xffffffffu, mx0, 2));
        mx1 = fmaxf(mx1, __shfl_xor_sync(0xffffffffu, mx1, 1));
        mx1 = fmaxf(mx1, __shfl_xor_sync(0xffffffffu, mx1, 2));

        float mn0 = fmaxf(m0, mx0), mn1 = fmaxf(m1, mx1);
        float cr0 = __expf(m0 - mn0), cr1 = __expf(m1 - mn1);
        l0 *= cr0; l1 *= cr1;
        m0 = mn0;  m1 = mn1;

        // exp -> P fragments directly in registers (no smem round trip):
        // aph[nt][0] = rows g pair, aph[nt][1] = rows g+8 pair.
        uint32_t aph[8][2], apl[8][2];
        float ps0 = 0.f, ps1 = 0.f;
#pragma unroll
        for (int nt = 0; nt < 8; ++nt) {
            ofr[nt][0] *= cr0; ofr[nt][1] *= cr0;
            ofr[nt][2] *= cr1; ofr[nt][3] *= cr1;
            float p0 = __expf(sfr[nt][0] - m0);
            float p1 = __expf(sfr[nt][1] - m0);
            float p2 = __expf(sfr[nt][2] - m1);
            float p3 = __expf(sfr[nt][3] - m1);
            ps0 += p0 + p1; ps1 += p2 + p3;
            bsplit2(p0, p1, aph[nt][0], apl[nt][0]);
            bsplit2(p2, p3, aph[nt][1], apl[nt][1]);
        }
        ps0 += __shfl_xor_sync(0xffffffffu, ps0, 1);
        ps0 += __shfl_xor_sync(0xffffffffu, ps0, 2);
        ps1 += __shfl_xor_sync(0xffffffffu, ps1, 1);
        ps1 += __shfl_xor_sync(0xffffffffu, ps1, 2);
        l0 += ps0; l1 += ps1;

        // O += P V  (V fragments via ldmatrix.trans on K-major V rows)
#pragma unroll
        for (int kc = 0; kc < 4; ++kc) {
            uint32_t pah[4] = {aph[2 * kc][0], aph[2 * kc][1],
                               aph[2 * kc + 1][0], aph[2 * kc + 1][1]};
            uint32_t pal[4] = {apl[2 * kc][0], apl[2 * kc][1],
                               apl[2 * kc + 1][0], apl[2 * kc + 1][1]};
            uint32_t vh2[8][2], vl2[8][2];
#pragma unroll
            for (int nt = 0; nt < 8; ++nt) {
                ldm_x2t(vh2[nt], stbVH + kc * (16 * 144) + nt * 16);
                ldm_x2t(vl2[nt], stbVL + kc * (16 * 144) + nt * 16);
            }
#pragma unroll
            for (int nt = 0; nt < 8; ++nt)
                mma_bf16(ofr[nt], pah, vh2[nt][0], vh2[nt][1]);
#pragma unroll
            for (int nt = 0; nt < 8; ++nt)
                mma_bf16(ofr[nt], pah, vl2[nt][0], vl2[nt][1]);
#pragma unroll
            for (int nt = 0; nt < 8; ++nt)
                mma_bf16(ofr[nt], pal, vh2[nt][0], vh2[nt][1]);
        }
    }
#undef KV_ISSUE

    // Epilogue: normalize, split-write attention output
    float inv0 = 1.f / l0, inv1 = 1.f / l1;
    size_t row0 = (size_t)(qrow0 * BATCH + b) * (DMODEL / 2);
    size_t row1 = (size_t)(qrow1 * BATCH + b) * (DMODEL / 2);
#pragma unroll
    for (int nt = 0; nt < 8; ++nt) {
        int pcol = h * 32 + nt * 4 + q4;
        uint32_t hi, lo;
        bsplit2(ofr[nt][0] * inv0, ofr[nt][1] * inv0, hi, lo);
        ((uint32_t*)Oh)[row0 + pcol] = hi;
        ((uint32_t*)Ol)[row0 + pcol] = lo;
        bsplit2(ofr[nt][2] * inv1, ofr[nt][3] * inv1, hi, lo);
        ((uint32_t*)Oh)[row1 + pcol] = hi;
        ((uint32_t*)Ol)[row1 + pcol] = lo;
    }
}

// ---------------------------------------------------------------------------
extern "C" void kernel_launch(void* const* d_in, const int* in_sizes, int n_in,
                              void* d_out, int out_size)
{
    const float* x     = (const float*)d_in[0];   // [S,B,D]
    const float* w_qkv = (const float*)d_in[1];   // [3D,D]
    const float* w_out = (const float*)d_in[2];   // [D,D]
    const float* b_out = (const float*)d_in[3];   // [D]
    float* out = (float*)d_out;

    __nv_bfloat16 *xh, *xl, *wqh, *wql, *woh, *wol, *qkvh, *qkvl, *ah, *al;
    cudaGetSymbolAddress((void**)&xh,   g_xh);
    cudaGetSymbolAddress((void**)&xl,   g_xl);
    cudaGetSymbolAddress((void**)&wqh,  g_wqh);
    cudaGetSymbolAddress((void**)&wql,  g_wql);
    cudaGetSymbolAddress((void**)&woh,  g_woh);
    cudaGetSymbolAddress((void**)&wol,  g_wol);
    cudaGetSymbolAddress((void**)&qkvh, g_qkvh);
    cudaGetSymbolAddress((void**)&qkvl, g_qkvl);
    cudaGetSymbolAddress((void**)&ah,   g_ah);
    cudaGetSymbolAddress((void**)&al,   g_al);

    cudaFuncSetAttribute(gemm_bf16x3,
                         cudaFuncAttributeMaxDynamicSharedMemorySize, G_SMEM_BYTES);
    cudaFuncSetAttribute(attn_bf16,
                         cudaFuncAttributeMaxDynamicSharedMemorySize, ATT_SMEM_BYTES);

    // 0) Split inputs to bf16 hi/lo
    {
        int n1 = MROWS * DMODEL;        // x
        int n2 = 3 * DMODEL * DMODEL;   // w_qkv
        int n3 = DMODEL * DMODEL;       // w_out
        split_kernel<<<(n1 / 4 + 255) / 256, 256>>>(x, xh, xl, n1);
        split_kernel<<<(n2 / 4 + 255) / 256, 256>>>(w_qkv, wqh, wql, n2);
        split_kernel<<<(n3 / 4 + 255) / 256, 256>>>(w_out, woh, wol, n3);
    }

    // 1) QKV projection -> split qkv (Q cols scaled by 0.125)
    gemm_bf16x3<<<dim3(3 * DMODEL / 64, MROWS / 128), 128, G_SMEM_BYTES>>>(
        xh, xl, wqh, wql, nullptr, nullptr, qkvh, qkvl,
        MROWS, 3 * DMODEL, DMODEL, DMODEL);

    // 2) Causal flash attention -> split attention output
    attn_bf16<<<dim3(S_LEN / 64, BATCH * NH), 128, ATT_SMEM_BYTES>>>(
        qkvh, qkvl, ah, al);

    // 3) Output projection + bias -> fp32 out
    gemm_bf16x3<<<dim3(DMODEL / 64, MROWS / 128), 128, G_SMEM_BYTES>>>(
        ah, al, woh, wol, b_out, out, nullptr, nullptr,
        MROWS, DMODEL, DMODEL, 0);
}